// round 9
// baseline (speedup 1.0000x reference)
#include <cuda_runtime.h>
#include <cuda_bf16.h>
#include <math.h>
#include <stdint.h>

#define BSZ    2048
#define A_N    32
#define ROWS   (BSZ*A_N)        // 65536
#define HIDN   256
#define NHEAD  4
#define TOPKN  8
#define NACT   20
#define NEGV   (-1e10f)

// ---------------- scratch ---------------------------------------------------
// blocked hi/lo bf16 layout: [row][K/32 blocks][hi x32 | lo x32], row stride 2K
__device__ __nv_bfloat16 g_InHL [(size_t)ROWS*512];
__device__ __nv_bfloat16 g_HidHL[(size_t)ROWS*512];
__device__ __nv_bfloat16 g_XHL  [(size_t)ROWS*512];
__device__ __nv_bfloat16 g_CCHL [(size_t)ROWS*640];
__device__ __nv_bfloat16 g_W1HL [256*512];
__device__ __nv_bfloat16 g_WiHL [768*512];
__device__ __nv_bfloat16 g_WhHL [768*512];
__device__ __nv_bfloat16 g_QKVHL[192*512];
__device__ __nv_bfloat16 g_P1WHL[256*640];
__device__ float g_Q [(size_t)ROWS*64];
__device__ float g_K [(size_t)ROWS*64];
__device__ float g_V [(size_t)ROWS*64];
__device__ float g_GT[(size_t)ROWS*NHEAD];
__device__ float g_P1[(size_t)ROWS*HIDN];

// ---------------- helpers ---------------------------------------------------
__device__ __forceinline__ void split2(float x0, float x1, uint32_t& wh, uint32_t& wl) {
    __nv_bfloat16 h0 = __float2bfloat16_rn(x0);
    __nv_bfloat16 h1 = __float2bfloat16_rn(x1);
    __nv_bfloat16 l0 = __float2bfloat16_rn(x0 - __bfloat162float(h0));
    __nv_bfloat16 l1 = __float2bfloat16_rn(x1 - __bfloat162float(h1));
    __nv_bfloat162 H = __nv_bfloat162(h0, h1);
    __nv_bfloat162 L = __nv_bfloat162(l0, l1);
    wh = *reinterpret_cast<uint32_t*>(&H);
    wl = *reinterpret_cast<uint32_t*>(&L);
}

__device__ __forceinline__ float2 rec2(uint32_t h, uint32_t l) {
    __nv_bfloat162 H = *reinterpret_cast<__nv_bfloat162*>(&h);
    __nv_bfloat162 L = *reinterpret_cast<__nv_bfloat162*>(&l);
    return make_float2(__bfloat162float(H.x) + __bfloat162float(L.x),
                       __bfloat162float(H.y) + __bfloat162float(L.y));
}

__device__ __forceinline__ void mma_bf16(float* d, const uint32_t* a, const uint32_t* b) {
    asm volatile(
        "mma.sync.aligned.m16n8k16.row.col.f32.bf16.bf16.f32 "
        "{%0,%1,%2,%3}, {%4,%5,%6,%7}, {%8,%9}, {%0,%1,%2,%3};"
        : "+f"(d[0]), "+f"(d[1]), "+f"(d[2]), "+f"(d[3])
        : "r"(a[0]), "r"(a[1]), "r"(a[2]), "r"(a[3]),
          "r"(b[0]), "r"(b[1]));
}

__device__ __forceinline__ void ldsm_x4(uint32_t& r0, uint32_t& r1, uint32_t& r2, uint32_t& r3,
                                        uint32_t addr) {
    asm volatile("ldmatrix.sync.aligned.m8n8.x4.shared.b16 {%0,%1,%2,%3}, [%4];"
        : "=r"(r0), "=r"(r1), "=r"(r2), "=r"(r3) : "r"(addr));
}

__device__ __forceinline__ void cp16(uint32_t dst, const void* src) {
    asm volatile("cp.async.cg.shared.global [%0], [%1], 16;" :: "r"(dst), "l"(src));
}
__device__ __forceinline__ void cp_commit() {
    asm volatile("cp.async.commit_group;" ::: "memory");
}
template<int N>
__device__ __forceinline__ void cp_wait() {
    asm volatile("cp.async.wait_group %0;" :: "n"(N) : "memory");
}

__device__ __forceinline__ float sigm(float x) { return 1.f/(1.f + expf(-x)); }

// swizzled smem byte offset for (row, 16B-chunk) within a 128B-row tile
__device__ __forceinline__ uint32_t swz(int row, int ch) {
    return (uint32_t)(row * 128 + ((ch ^ (row & 7)) << 4));
}

// ---------------- conversions to blocked hi/lo bf16 -------------------------
__device__ __forceinline__ void store_blk(__nv_bfloat16* dst, int c4, float4 v) {
    uint32_t h0, l0, h1, l1;
    split2(v.x, v.y, h0, l0);
    split2(v.z, v.w, h1, l1);
    __nv_bfloat16* base = dst + ((c4 >> 5) * 64) + (c4 & 31);
    *(uint32_t*)(base)      = h0; *(uint32_t*)(base + 2)  = h1;
    *(uint32_t*)(base + 32) = l0; *(uint32_t*)(base + 34) = l1;
}

// activations: inputs + hidden in one launch
__global__ void __launch_bounds__(256)
conv_acts(const float4* __restrict__ inA, __nv_bfloat16* __restrict__ dA,
          const float4* __restrict__ inB, __nv_bfloat16* __restrict__ dB)
{
    int i = blockIdx.x * blockDim.x + threadIdx.x;
    int n4 = ROWS * 64;
    const float4* src; __nv_bfloat16* dst; int j;
    if (i < n4) { src = inA; dst = dA; j = i; }
    else if (i < 2 * n4) { src = inB; dst = dB; j = i - n4; }
    else return;
    int r = j >> 6, c4 = (j & 63) << 2;
    store_blk(dst + (size_t)r * 512, c4, src[j]);
}

// all K=256 weights in one launch
__global__ void __launch_bounds__(256)
conv_wts(const float* __restrict__ fc1w, const float* __restrict__ wih,
         const float* __restrict__ whh, const float* __restrict__ qw,
         const float* __restrict__ kw, const float* __restrict__ vw,
         __nv_bfloat16* __restrict__ W1, __nv_bfloat16* __restrict__ Wi,
         __nv_bfloat16* __restrict__ Wh, __nv_bfloat16* __restrict__ QKV)
{
    int i = blockIdx.x * blockDim.x + threadIdx.x;
    if (i >= 1984 * 64) return;
    int row = i >> 6, c4 = (i & 63) << 2;
    const float* src; __nv_bfloat16* dst;
    if (row < 256)       { src = fc1w + (size_t)row * 256;        dst = W1 + (size_t)row * 512; }
    else if (row < 1024) { int r = row - 256;  src = wih + (size_t)r * 256; dst = Wi + (size_t)r * 512; }
    else if (row < 1792) { int r = row - 1024; src = whh + (size_t)r * 256; dst = Wh + (size_t)r * 512; }
    else {
        int r = row - 1792;
        src = (r < 64) ? (qw + (size_t)r * 256)
            : (r < 128) ? (kw + (size_t)(r - 64) * 256)
                        : (vw + (size_t)(r - 128) * 256);
        dst = QKV + (size_t)r * 512;
    }
    store_blk(dst, c4, *(const float4*)(src + c4));
}

// p1 weights (K=320)
__global__ void __launch_bounds__(256)
conv_p1w(const float4* __restrict__ src, __nv_bfloat16* __restrict__ dst)
{
    int i = blockIdx.x * blockDim.x + threadIdx.x;
    if (i >= 256 * 80) return;
    int r = i / 80, c4 = (i - r * 80) << 2;
    store_blk(dst + (size_t)r * 640, c4, src[i]);
}

// ================= generic GEMM: 128x64 tile, cp.async 3-stage ==============
#define GST_B 24576
#define GW_OFF 16384

template<int ACT, int OUTHL>
__global__ void __launch_bounds__(256,2)
gemmHL(const __nv_bfloat16* __restrict__ A, int as,
       const __nv_bfloat16* __restrict__ W, int ws,
       const float* __restrict__ bias,
       float* __restrict__ Cf, int ldc,
       __nv_bfloat16* __restrict__ Chl, int os,
       int ntiles)
{
    extern __shared__ char smc[];
    const uint32_t smb = (uint32_t)__cvta_generic_to_shared(smc);
    const int tid = threadIdx.x, lane = tid & 31, warp = tid >> 5;
    const int group = lane >> 2, tig = lane & 3;
    const int wm = warp >> 1, wn = warp & 1;
    const int m0 = blockIdx.y * 128, n0 = blockIdx.x * 64;

    const int arow = (lane & 7) + ((lane >> 3) & 1) * 8;
    const int akc  = (lane >> 4) & 1;
    const int brow = (lane & 7) + ((lane >> 4) & 1) * 8;
    const int bkc  = (lane >> 3) & 1;

    float acc[2][4][4];
    #pragma unroll
    for (int mi = 0; mi < 2; mi++)
        #pragma unroll
        for (int ni = 0; ni < 4; ni++)
            #pragma unroll
            for (int j = 0; j < 4; j++) acc[mi][ni][j] = 0.f;

    const int lrow = tid >> 3, lch = tid & 7;

    #define G_ISSUE(t) {                                                        \
        uint32_t sb_ = smb + ((t) % 3) * GST_B;                                 \
        _Pragma("unroll")                                                       \
        for (int i_ = 0; i_ < 4; i_++) {                                        \
            int row_ = lrow + i_ * 32;                                          \
            cp16(sb_ + swz(row_, lch),                                          \
                 A + (size_t)(m0 + row_) * as + (t) * 64 + lch * 8);            \
        }                                                                       \
        _Pragma("unroll")                                                       \
        for (int i_ = 0; i_ < 2; i_++) {                                        \
            int row_ = lrow + i_ * 32;                                          \
            cp16(sb_ + GW_OFF + swz(row_, lch),                                 \
                 W + (size_t)(n0 + row_) * ws + (t) * 64 + lch * 8);            \
        }                                                                       \
        cp_commit();                                                            \
    }

    G_ISSUE(0);
    if (ntiles > 1) G_ISSUE(1);

    for (int t = 0; t < ntiles; t++) {
        if (t + 1 < ntiles) cp_wait<1>(); else cp_wait<0>();
        __syncthreads();
        if (t + 2 < ntiles) G_ISSUE(t + 2);

        const uint32_t sb = smb + (t % 3) * GST_B;
        #pragma unroll
        for (int kk = 0; kk < 2; kk++) {
            uint32_t aH[2][4], aL[2][4];
            #pragma unroll
            for (int mi = 0; mi < 2; mi++) {
                int r = wm * 32 + mi * 16 + arow;
                int ch = 2 * kk + akc;
                ldsm_x4(aH[mi][0], aH[mi][1], aH[mi][2], aH[mi][3], sb + swz(r, ch));
                ldsm_x4(aL[mi][0], aL[mi][1], aL[mi][2], aL[mi][3], sb + swz(r, ch + 4));
            }
            #pragma unroll
            for (int j = 0; j < 2; j++) {
                int r = wn * 32 + j * 16 + brow;
                int ch = 2 * kk + bkc;
                uint32_t bH[2][2], bL[2][2];
                ldsm_x4(bH[0][0], bH[0][1], bH[1][0], bH[1][1], sb + GW_OFF + swz(r, ch));
                ldsm_x4(bL[0][0], bL[0][1], bL[1][0], bL[1][1], sb + GW_OFF + swz(r, ch + 4));
                #pragma unroll
                for (int mi = 0; mi < 2; mi++)
                    #pragma unroll
                    for (int p = 0; p < 2; p++) {
                        int ni = 2 * j + p;
                        mma_bf16(acc[mi][ni], aH[mi], bL[p]);
                        mma_bf16(acc[mi][ni], aL[mi], bH[p]);
                        mma_bf16(acc[mi][ni], aH[mi], bH[p]);
                    }
            }
        }
    }
    #undef G_ISSUE

    #pragma unroll
    for (int mi = 0; mi < 2; mi++) {
        #pragma unroll
        for (int ni = 0; ni < 4; ni++) {
            int row = m0 + wm * 32 + mi * 16 + group;
            int col = n0 + wn * 32 + ni * 8 + 2 * tig;
            float b0 = bias[col], b1 = bias[col + 1];
            float v0 = acc[mi][ni][0] + b0;
            float v1 = acc[mi][ni][1] + b1;
            float v2 = acc[mi][ni][2] + b0;
            float v3 = acc[mi][ni][3] + b1;
            if (ACT == 1) {
                v0 = fmaxf(v0, 0.f); v1 = fmaxf(v1, 0.f);
                v2 = fmaxf(v2, 0.f); v3 = fmaxf(v3, 0.f);
            }
            if (OUTHL == 0) {
                *(float2*)(Cf + (size_t)row * ldc + col)       = make_float2(v0, v1);
                *(float2*)(Cf + (size_t)(row + 8) * ldc + col) = make_float2(v2, v3);
            } else {
                int b = col >> 5, pos = col & 31;
                uint32_t h, l;
                split2(v0, v1, h, l);
                *(uint32_t*)(Chl + (size_t)row * os + b * 64 + pos)      = h;
                *(uint32_t*)(Chl + (size_t)row * os + b * 64 + 32 + pos) = l;
                split2(v2, v3, h, l);
                *(uint32_t*)(Chl + (size_t)(row + 8) * os + b * 64 + pos)      = h;
                *(uint32_t*)(Chl + (size_t)(row + 8) * os + b * 64 + 32 + pos) = l;
            }
        }
    }
}

// ================= fused gi+gh GEMM + GRU ===================================
// CTA: 128 rows x 32 hcols x 3 gates; 512 threads (16 warps: 4m x 4n).
// acc_rz accumulates gi AND gh (GRU uses gi+gh for r,z); n-gate kept separate.
#define GG_X  0
#define GG_H  16384
#define GG_WI 32768
#define GG_WH 45056
#define GG_ST 57344     // bytes per stage

__global__ void __launch_bounds__(512,1)
gigh_gru(const __nv_bfloat16* __restrict__ XHL, const __nv_bfloat16* __restrict__ HidHL,
         const __nv_bfloat16* __restrict__ WiHL, const __nv_bfloat16* __restrict__ WhHL,
         const float* __restrict__ hidden,
         const float* __restrict__ bih, const float* __restrict__ bhh,
         __nv_bfloat16* __restrict__ cchl, float* __restrict__ hout)
{
    extern __shared__ char smc[];
    const uint32_t smb = (uint32_t)__cvta_generic_to_shared(smc);
    const int tid = threadIdx.x, lane = tid & 31, wid = tid >> 5;
    const int group = lane >> 2, tig = lane & 3;
    const int wm = wid >> 2, wn = wid & 3;
    const int m0  = blockIdx.y * 128;
    const int hb0 = blockIdx.x * 32;

    const int arow = (lane & 7) + ((lane >> 3) & 1) * 8;
    const int akc  = (lane >> 4) & 1;
    // B ldsm lane map: groups -> (hi k0, hi k1, lo k0, lo k1)
    const int brow = lane & 7;
    const int bko  = (lane >> 3) & 1;            // k-chunk within pair
    const int blo  = ((lane >> 4) & 1) * 4;      // lo-plane offset

    float acc_rz[2][2][4];     // [mi][gate r/z][frag] -- gi+gh combined
    float acc_gin[2][4], acc_ghn[2][4];
    #pragma unroll
    for (int mi = 0; mi < 2; mi++) {
        #pragma unroll
        for (int g = 0; g < 2; g++)
            #pragma unroll
            for (int j = 0; j < 4; j++) acc_rz[mi][g][j] = 0.f;
        #pragma unroll
        for (int j = 0; j < 4; j++) { acc_gin[mi][j] = 0.f; acc_ghn[mi][j] = 0.f; }
    }

    const int lrow = tid >> 3, lch = tid & 7;    // lrow 0..63

    #define GG_ISSUE(t) {                                                       \
        uint32_t sb_ = smb + ((t) % 3) * GG_ST;                                 \
        cp16(sb_ + GG_X + swz(lrow, lch),                                       \
             XHL + (size_t)(m0 + lrow) * 512 + (t) * 64 + lch * 8);             \
        cp16(sb_ + GG_X + swz(lrow + 64, lch),                                  \
             XHL + (size_t)(m0 + lrow + 64) * 512 + (t) * 64 + lch * 8);        \
        cp16(sb_ + GG_H + swz(lrow, lch),                                       \
             HidHL + (size_t)(m0 + lrow) * 512 + (t) * 64 + lch * 8);           \
        cp16(sb_ + GG_H + swz(lrow + 64, lch),                                  \
             HidHL + (size_t)(m0 + lrow + 64) * 512 + (t) * 64 + lch * 8);      \
        {   int wr_ = (lrow >> 5) * 256 + hb0 + (lrow & 31);                    \
            cp16(sb_ + GG_WI + swz(lrow, lch),                                  \
                 WiHL + (size_t)wr_ * 512 + (t) * 64 + lch * 8);                \
            cp16(sb_ + GG_WH + swz(lrow, lch),                                  \
                 WhHL + (size_t)wr_ * 512 + (t) * 64 + lch * 8);                \
        }                                                                       \
        if (tid < 256) {                                                        \
            int r2_ = 64 + (tid >> 3);                                          \
            int wr_ = 512 + hb0 + (r2_ & 31);                                   \
            cp16(sb_ + GG_WI + swz(r2_, lch),                                   \
                 WiHL + (size_t)wr_ * 512 + (t) * 64 + lch * 8);                \
            cp16(sb_ + GG_WH + swz(r2_, lch),                                   \
                 WhHL + (size_t)wr_ * 512 + (t) * 64 + lch * 8);                \
        }                                                                       \
        cp_commit();                                                            \
    }

    GG_ISSUE(0); GG_ISSUE(1);

    for (int t = 0; t < 8; t++) {
        if (t + 1 < 8) cp_wait<1>(); else cp_wait<0>();
        __syncthreads();
        if (t + 2 < 8) GG_ISSUE(t + 2);

        const uint32_t sb = smb + (t % 3) * GG_ST;
        #pragma unroll
        for (int kk = 0; kk < 2; kk++) {
            // B frags: Wi and Wh, per gate: one ldsm_x4 = {hi k0, hi k1, lo k0, lo k1}
            uint32_t biH[3][2], biL[3][2], bhH[3][2], bhL[3][2];
            #pragma unroll
            for (int g = 0; g < 3; g++) {
                int r = g * 32 + wn * 8 + brow;
                int ch = 2 * kk + bko + blo;
                ldsm_x4(biH[g][0], biH[g][1], biL[g][0], biL[g][1],
                        sb + GG_WI + swz(r, ch));
                ldsm_x4(bhH[g][0], bhH[g][1], bhL[g][0], bhL[g][1],
                        sb + GG_WH + swz(r, ch));
            }
            // gi: A = x
            #pragma unroll
            for (int mi = 0; mi < 2; mi++) {
                int r = wm * 32 + mi * 16 + arow;
                int ch = 2 * kk + akc;
                uint32_t aH[4], aL[4];
                ldsm_x4(aH[0], aH[1], aH[2], aH[3], sb + GG_X + swz(r, ch));
                ldsm_x4(aL[0], aL[1], aL[2], aL[3], sb + GG_X + swz(r, ch + 4));
                #pragma unroll
                for (int g = 0; g < 3; g++) {
                    float* d = (g < 2) ? acc_rz[mi][g] : acc_gin[mi];
                    mma_bf16(d, aH, biL[g]);
                    mma_bf16(d, aL, biH[g]);
                    mma_bf16(d, aH, biH[g]);
                }
            }
            // gh: A = hidden
            #pragma unroll
            for (int mi = 0; mi < 2; mi++) {
                int r = wm * 32 + mi * 16 + arow;
                int ch = 2 * kk + akc;
                uint32_t aH[4], aL[4];
                ldsm_x4(aH[0], aH[1], aH[2], aH[3], sb + GG_H + swz(r, ch));
                ldsm_x4(aL[0], aL[1], aL[2], aL[3], sb + GG_H + swz(r, ch + 4));
                #pragma unroll
                for (int g = 0; g < 3; g++) {
                    float* d = (g < 2) ? acc_rz[mi][g] : acc_ghn[mi];
                    mma_bf16(d, aH, bhL[g]);
                    mma_bf16(d, aL, bhH[g]);
                    mma_bf16(d, aH, bhH[g]);
                }
            }
        }
    }
    #undef GG_ISSUE

    // GRU epilogue (pure registers)
    const int blk = hb0 >> 5;
    #pragma unroll
    for (int mi = 0; mi < 2; mi++) {
        #pragma unroll
        for (int p = 0; p < 2; p++) {          // row, row+8
            int row = m0 + wm * 32 + mi * 16 + group + p * 8;
            #pragma unroll
            for (int c = 0; c < 2; c++) {      // two cols
                int fi = p * 2 + c;
                int hcol = hb0 + wn * 8 + 2 * tig + c;
                float sr = acc_rz[mi][0][fi] + bih[hcol]       + bhh[hcol];
                float sz = acc_rz[mi][1][fi] + bih[256 + hcol] + bhh[256 + hcol];
                float gin = acc_gin[mi][fi] + bih[512 + hcol];
                float ghn = acc_ghn[mi][fi] + bhh[512 + hcol];
                float r = sigm(sr);
                float z = sigm(sz);
                float n = tanhf(gin + r * ghn);
                float hin = hidden[(size_t)row * 256 + hcol];
                float h = (1.f - z) * n + z * hin;
                int pos = hcol & 31;
                __nv_bfloat16 hb = __float2bfloat16_rn(h);
                __nv_bfloat16 lb = __float2bfloat16_rn(h - __bfloat162float(hb));
                __nv_bfloat16* dp = cchl + (size_t)row * 640 + blk * 64 + pos;
                dp[0]  = hb;
                dp[32] = lb;
                if (hout) hout[(size_t)row * 256 + hcol] = h;
            }
        }
    }
}

// ================= fused q/k/v GEMM =========================================
#define FST_B 32768
#define FW_OFF 8192

__global__ void __launch_bounds__(256,2)
qkv_fused(const __nv_bfloat16* __restrict__ CChl, const __nv_bfloat16* __restrict__ QKVw,
          const float* __restrict__ qb, const float* __restrict__ kb,
          const float* __restrict__ vb,
          float* __restrict__ Q, float* __restrict__ K, float* __restrict__ V)
{
    extern __shared__ char smc[];
    const uint32_t smb = (uint32_t)__cvta_generic_to_shared(smc);

    const int tid = threadIdx.x, lane = tid & 31, warp = tid >> 5;
    const int group = lane >> 2, tig = lane & 3;
    const int wm = warp >> 2, wn = warp & 3;
    const int m0 = blockIdx.y * 64;

    const int arow = (lane & 7) + ((lane >> 3) & 1) * 8;
    const int akc  = (lane >> 4) & 1;
    const int brow = (lane & 7) + ((lane >> 4) & 1) * 8;
    const int bkc  = (lane >> 3) & 1;
    const int lrow = tid >> 3, lch = tid & 7;

    float acc[2][6][4];
    #pragma unroll
    for (int mi = 0; mi < 2; mi++)
        #pragma unroll
        for (int ni = 0; ni < 6; ni++)
            #pragma unroll
            for (int j = 0; j < 4; j++) acc[mi][ni][j] = 0.f;

    #define Q_ISSUE(t) {                                                        \
        uint32_t sb_ = smb + ((t) % 3) * FST_B;                                 \
        _Pragma("unroll")                                                       \
        for (int i_ = 0; i_ < 2; i_++) {                                        \
            int row_ = lrow + i_ * 32;                                          \
            cp16(sb_ + swz(row_, lch),                                          \
                 CChl + (size_t)(m0 + row_) * 640 + (t) * 64 + lch * 8);        \
        }                                                                       \
        _Pragma("unroll")                                                       \
        for (int i_ = 0; i_ < 6; i_++) {                                        \
            int row_ = lrow + i_ * 32;                                          \
            cp16(sb_ + FW_OFF + swz(row_, lch),                                 \
                 QKVw + (size_t)row_ * 512 + (t) * 64 + lch * 8);               \
        }                                                                       \
        cp_commit();                                                            \
    }

    Q_ISSUE(0); Q_ISSUE(1);

    for (int t = 0; t < 8; t++) {
        if (t + 1 < 8) cp_wait<1>(); else cp_wait<0>();
        __syncthreads();
        if (t + 2 < 8) Q_ISSUE(t + 2);

        const uint32_t sb = smb + (t % 3) * FST_B;
        #pragma unroll
        for (int kk = 0; kk < 2; kk++) {
            uint32_t aH[2][4], aL[2][4];
            #pragma unroll
            for (int mi = 0; mi < 2; mi++) {
                int r = wm * 32 + mi * 16 + arow;
                int ch = 2 * kk + akc;
                ldsm_x4(aH[mi][0], aH[mi][1], aH[mi][2], aH[mi][3], sb + swz(r, ch));
                ldsm_x4(aL[mi][0], aL[mi][1], aL[mi][2], aL[mi][3], sb + swz(r, ch + 4));
            }
            #pragma unroll
            for (int j = 0; j < 3; j++) {
                int r = wn * 48 + j * 16 + brow;
                int ch = 2 * kk + bkc;
                uint32_t bH[2][2], bL[2][2];
                ldsm_x4(bH[0][0], bH[0][1], bH[1][0], bH[1][1], sb + FW_OFF + swz(r, ch));
                ldsm_x4(bL[0][0], bL[0][1], bL[1][0], bL[1][1], sb + FW_OFF + swz(r, ch + 4));
                #pragma unroll
                for (int mi = 0; mi < 2; mi++)
                    #pragma unroll
                    for (int p = 0; p < 2; p++) {
                        int ni = 2 * j + p;
                        mma_bf16(acc[mi][ni], aH[mi], bL[p]);
                        mma_bf16(acc[mi][ni], aL[mi], bH[p]);
                        mma_bf16(acc[mi][ni], aH[mi], bH[p]);
                    }
            }
        }
    }
    #undef Q_ISSUE

    #pragma unroll
    for (int mi = 0; mi < 2; mi++) {
        #pragma unroll
        for (int ni = 0; ni < 6; ni++) {
            int row = m0 + wm * 32 + mi * 16 + group;
            int col = wn * 48 + ni * 8 + 2 * tig;
            float* dst; const float* bs; int oc;
            if (col < 64)       { dst = Q; bs = qb; oc = col; }
            else if (col < 128) { dst = K; bs = kb; oc = col - 64; }
            else                { dst = V; bs = vb; oc = col - 128; }
            float b0 = bs[oc], b1 = bs[oc + 1];
            *(float2*)(dst + (size_t)row * 64 + oc) =
                make_float2(acc[mi][ni][0] + b0, acc[mi][ni][1] + b1);
            *(float2*)(dst + (size_t)(row + 8) * 64 + oc) =
                make_float2(acc[mi][ni][2] + b0, acc[mi][ni][3] + b1);
        }
    }
}

// ---------------- head gates (reads hi/lo CC) --------------------------------
__global__ void __launch_bounds__(256)
gate_kernel(const __nv_bfloat16* __restrict__ CChl, const float* __restrict__ gw,
            const float* __restrict__ gb, float* __restrict__ gate)
{
    int gwp  = (int)(((size_t)blockIdx.x*blockDim.x + threadIdx.x) >> 5);
    int lane = threadIdx.x & 31;
    if (gwp >= ROWS) return;
    int o = lane >> 3, part = lane & 7;
    const __nv_bfloat16* hr = CChl + (size_t)gwp * 640;
    const float* wr = gw + o * 256;
    float s = 0.f;
    #pragma unroll
    for (int j = 0; j < 8; j++) {
        int k = part * 4 + 32 * j;
        uint32_t h0 = *(const uint32_t*)(hr + j * 64 + part * 4);
        uint32_t h1 = *(const uint32_t*)(hr + j * 64 + part * 4 + 2);
        uint32_t l0 = *(const uint32_t*)(hr + j * 64 + 32 + part * 4);
        uint32_t l1 = *(const uint32_t*)(hr + j * 64 + 32 + part * 4 + 2);
        float2 a = rec2(h0, l0), b = rec2(h1, l1);
        float4 wv = *(const float4*)(wr + k);
        s += a.x*wv.x + a.y*wv.y + b.x*wv.z + b.y*wv.w;
    }
    s += __shfl_down_sync(0xffffffffu, s, 4, 8);
    s += __shfl_down_sync(0xffffffffu, s, 2, 8);
    s += __shfl_down_sync(0xffffffffu, s, 1, 8);
    if (part == 0) gate[(size_t)gwp*NHEAD + o] = sigm(s + gb[o]);
}

// ---------------- per-batch sparse attention ---------------------------------
__global__ void __launch_bounds__(256)
attn_kernel(const float* __restrict__ Q, const float* __restrict__ K,
            const float* __restrict__ V, const float* __restrict__ gate,
            __nv_bfloat16* __restrict__ cchl)
{
    __shared__ float QS[32][65], KS[32][65], VS[32][65];
    __shared__ float SS[4][32][33];
    const int b   = blockIdx.x;
    const int tid = threadIdx.x;
    const float* Qb = Q + (size_t)b*2048;
    const float* Kb = K + (size_t)b*2048;
    const float* Vb = V + (size_t)b*2048;

    for (int i = tid; i < 2048; i += 256) {
        int r = i >> 6, c = i & 63;
        QS[r][c] = Qb[i]; KS[r][c] = Kb[i]; VS[r][c] = Vb[i];
    }
    __syncthreads();

    for (int i = tid; i < 4096; i += 256) {
        int q = i >> 7, rem = i & 127;
        int h = rem >> 5, k = rem & 31;
        float s;
        if (q == k) s = NEGV;
        else {
            float acc = 0.f;
            #pragma unroll
            for (int d = 0; d < 16; d++) acc += QS[q][h*16+d]*KS[k][h*16+d];
            s = 0.25f*acc;
        }
        SS[h][q][k] = s;
    }
    __syncthreads();

    if (tid < 128) {
        int h = tid >> 5, q = tid & 31;
        float v[32];
        #pragma unroll
        for (int k = 0; k < 32; k++) v[k] = SS[h][q][k];
        float maxv = -INFINITY;
        unsigned keep = 0u;
        #pragma unroll
        for (int k = 0; k < 32; k++) {
            int cnt = 0;
            #pragma unroll
            for (int j = 0; j < 32; j++) cnt += (v[j] > v[k]);
            if (cnt < TOPKN) { keep |= (1u << k); maxv = fmaxf(maxv, v[k]); }
        }
        float e[32], sum = 0.f;
        #pragma unroll
        for (int k = 0; k < 32; k++) {
            float ek = ((keep >> k) & 1u) ? expf(v[k] - maxv) : 0.f;
            e[k] = ek; sum += ek;
        }
        float inv = 1.f / sum;
        #pragma unroll
        for (int k = 0; k < 32; k++) SS[h][q][k] = e[k]*inv;
    }
    __syncthreads();

    for (int i = tid; i < 2048; i += 256) {
        int q = i >> 6, hv = i & 63, h = hv >> 4;
        float acc = 0.f;
        #pragma unroll
        for (int k = 0; k < 32; k++) acc += SS[h][q][k]*VS[k][hv];
        float gt = gate[((size_t)b*32 + q)*NHEAD + h];
        float g = acc * gt;
        int c = 256 + hv;
        int blk = c >> 5, pos = c & 31;
        __nv_bfloat16 hb = __float2bfloat16_rn(g);
        __nv_bfloat16 lb = __float2bfloat16_rn(g - __bfloat162float(hb));
        __nv_bfloat16* dp = cchl + ((size_t)b*32 + q) * 640 + blk * 64 + pos;
        dp[0]  = hb;
        dp[32] = lb;
    }
}

// ---------------- p2 head ---------------------------------------------------
__global__ void __launch_bounds__(256)
p2_kernel(const float* __restrict__ P1, const float* __restrict__ w,
          const float* __restrict__ b, float* __restrict__ out)
{
    __shared__ float WS[20*257];
    int tid = threadIdx.x;
    for (int i = tid; i < 20*256; i += 256) {
        int o = i >> 8, k = i & 255;
        WS[o*257 + k] = w[i];
    }
    __syncthreads();
    int r = tid / 20, o = tid % 20;
    int row = blockIdx.x*12 + r;
    if (tid >= 240 || row >= ROWS) return;
    const float* a  = P1 + (size_t)row*256;
    const float* wr = WS + o*257;
    float s = b[o];
    #pragma unroll 4
    for (int k = 0; k < 256; k += 4) {
        float4 av = *(const float4*)(a + k);
        s += av.x*wr[k] + av.y*wr[k+1] + av.z*wr[k+2] + av.w*wr[k+3];
    }
    out[(size_t)row*NACT + o] = s;
}

// ---------------------------------------------------------------------------
extern "C" void kernel_launch(void* const* d_in, const int* in_sizes, int n_in,
                              void* d_out, int out_size)
{
    const float* inputs = (const float*)d_in[0];
    const float* hidden = (const float*)d_in[1];
    const float* fc1_w  = (const float*)d_in[2];
    const float* fc1_b  = (const float*)d_in[3];
    const float* w_ih   = (const float*)d_in[4];
    const float* w_hh   = (const float*)d_in[5];
    const float* b_ih   = (const float*)d_in[6];
    const float* b_hh   = (const float*)d_in[7];
    const float* q_w    = (const float*)d_in[8];
    const float* q_b    = (const float*)d_in[9];
    const float* k_w    = (const float*)d_in[10];
    const float* k_b    = (const float*)d_in[11];
    const float* v_w    = (const float*)d_in[12];
    const float* v_b    = (const float*)d_in[13];
    const float* g_w    = (const float*)d_in[14];
    const float* g_b    = (const float*)d_in[15];
    const float* p1_w   = (const float*)d_in[16];
    const float* p1_b   = (const float*)d_in[17];
    const float* p2_w   = (const float*)d_in[18];
    const float* p2_b   = (const float*)d_in[19];

    float *Q, *K, *V, *GT, *P1;
    __nv_bfloat16 *InHL, *HidHL, *XHL, *CCHL, *W1HL, *WiHL, *WhHL, *QKVHL, *P1WHL;
    cudaGetSymbolAddress((void**)&Q,  g_Q);
    cudaGetSymbolAddress((void**)&K,  g_K);
    cudaGetSymbolAddress((void**)&V,  g_V);
    cudaGetSymbolAddress((void**)&GT, g_GT);
    cudaGetSymbolAddress((void**)&P1, g_P1);
    cudaGetSymbolAddress((void**)&InHL,  g_InHL);
    cudaGetSymbolAddress((void**)&HidHL, g_HidHL);
    cudaGetSymbolAddress((void**)&XHL,   g_XHL);
    cudaGetSymbolAddress((void**)&CCHL,  g_CCHL);
    cudaGetSymbolAddress((void**)&W1HL,  g_W1HL);
    cudaGetSymbolAddress((void**)&WiHL,  g_WiHL);
    cudaGetSymbolAddress((void**)&WhHL,  g_WhHL);
    cudaGetSymbolAddress((void**)&QKVHL, g_QKVHL);
    cudaGetSymbolAddress((void**)&P1WHL, g_P1WHL);

    float* out  = (float*)d_out;
    float* hout = nullptr;
    long long need = (long long)ROWS*NACT + (long long)ROWS*HIDN;
    if ((long long)out_size >= need) hout = out + (size_t)ROWS*NACT;

    const int gsm  = 3 * GST_B;   // 73728
    const int fsm  = 3 * FST_B;   // 98304
    const int ggsm = 3 * GG_ST;   // 172032
    static int smem_set = 0;
    if (!smem_set) {
        cudaFuncSetAttribute(gemmHL<1,0>, cudaFuncAttributeMaxDynamicSharedMemorySize, gsm);
        cudaFuncSetAttribute(gemmHL<1,1>, cudaFuncAttributeMaxDynamicSharedMemorySize, gsm);
        cudaFuncSetAttribute(gigh_gru, cudaFuncAttributeMaxDynamicSharedMemorySize, ggsm);
        cudaFuncSetAttribute(qkv_fused, cudaFuncAttributeMaxDynamicSharedMemorySize, fsm);
        smem_set = 1;
    }

    dim3 thr(256);

    // 0) conversions (3 launches)
    conv_acts<<<(2*ROWS*64 + 255)/256, thr>>>((const float4*)inputs, InHL,
                                              (const float4*)hidden, HidHL);
    conv_wts<<<(1984*64 + 255)/256, thr>>>(fc1_w, w_ih, w_hh, q_w, k_w, v_w,
                                           W1HL, WiHL, WhHL, QKVHL);
    conv_p1w<<<(256*80 + 255)/256, thr>>>((const float4*)p1_w, P1WHL);

    // 1) x = relu(inputs @ fc1_w^T + fc1_b) -> XHL
    gemmHL<1,1><<<dim3(4, ROWS/128), thr, gsm>>>(InHL, 512, W1HL, 512, fc1_b,
                                                 nullptr, 0, XHL, 512, 8);
    // 2+3) fused gi+gh GEMM + GRU -> CCHL blocks 0-7 + hout
    gigh_gru<<<dim3(8, ROWS/128), dim3(512), ggsm>>>(XHL, HidHL, WiHL, WhHL,
                                                     hidden, b_ih, b_hh, CCHL, hout);
    // 4) fused q/k/v projections
    qkv_fused<<<dim3(1, ROWS/64), thr, fsm>>>(CCHL, QKVHL, q_b, k_b, v_b, Q, K, V);
    // 5) head gates
    gate_kernel<<<(ROWS*32)/256, thr>>>(CCHL, g_w, g_b, GT);
    // 6) sparse top-8 attention -> CCHL blocks 8-9
    attn_kernel<<<BSZ, thr>>>(Q, K, V, GT, CCHL);
    // 7) p1 = relu(CC @ p1_w^T + p1_b) -> P1 (f32)
    gemmHL<1,0><<<dim3(4, ROWS/128), thr, gsm>>>(CCHL, 640, P1WHL, 640, p1_b,
                                                 P1, 256, nullptr, 0, 10);
    // 8) logits
    p2_kernel<<<(ROWS + 11)/12, thr>>>(P1, p2_w, p2_b, out);
}

// round 10
// speedup vs baseline: 1.0323x; 1.0323x over previous
#include <cuda_runtime.h>
#include <cuda_bf16.h>
#include <math.h>
#include <stdint.h>

#define BSZ    2048
#define A_N    32
#define ROWS   (BSZ*A_N)        // 65536
#define HIDN   256
#define NHEAD  4
#define TOPKN  8
#define NACT   20
#define NEGV   (-1e10f)

// ---------------- scratch ---------------------------------------------------
__device__ __nv_bfloat16 g_InHL [(size_t)ROWS*512];
__device__ __nv_bfloat16 g_HidHL[(size_t)ROWS*512];
__device__ __nv_bfloat16 g_XHL  [(size_t)ROWS*512];
__device__ __nv_bfloat16 g_CCHL [(size_t)ROWS*640];
__device__ __nv_bfloat16 g_W1HL [256*512];
__device__ __nv_bfloat16 g_WiHL [768*512];
__device__ __nv_bfloat16 g_WhHL [768*512];
__device__ __nv_bfloat16 g_QKVHL[192*512];
__device__ __nv_bfloat16 g_P1WHL[256*640];
__device__ float g_GI[(size_t)ROWS*3*HIDN];
__device__ float g_GT[(size_t)ROWS*NHEAD];
__device__ float g_P1[(size_t)ROWS*HIDN];

// ---------------- helpers ---------------------------------------------------
__device__ __forceinline__ void split2(float x0, float x1, uint32_t& wh, uint32_t& wl) {
    __nv_bfloat16 h0 = __float2bfloat16_rn(x0);
    __nv_bfloat16 h1 = __float2bfloat16_rn(x1);
    __nv_bfloat16 l0 = __float2bfloat16_rn(x0 - __bfloat162float(h0));
    __nv_bfloat16 l1 = __float2bfloat16_rn(x1 - __bfloat162float(h1));
    __nv_bfloat162 H = __nv_bfloat162(h0, h1);
    __nv_bfloat162 L = __nv_bfloat162(l0, l1);
    wh = *reinterpret_cast<uint32_t*>(&H);
    wl = *reinterpret_cast<uint32_t*>(&L);
}

__device__ __forceinline__ float2 rec2(uint32_t h, uint32_t l) {
    __nv_bfloat162 H = *reinterpret_cast<__nv_bfloat162*>(&h);
    __nv_bfloat162 L = *reinterpret_cast<__nv_bfloat162*>(&l);
    return make_float2(__bfloat162float(H.x) + __bfloat162float(L.x),
                       __bfloat162float(H.y) + __bfloat162float(L.y));
}

__device__ __forceinline__ void mma_bf16(float* d, const uint32_t* a, const uint32_t* b) {
    asm volatile(
        "mma.sync.aligned.m16n8k16.row.col.f32.bf16.bf16.f32 "
        "{%0,%1,%2,%3}, {%4,%5,%6,%7}, {%8,%9}, {%0,%1,%2,%3};"
        : "+f"(d[0]), "+f"(d[1]), "+f"(d[2]), "+f"(d[3])
        : "r"(a[0]), "r"(a[1]), "r"(a[2]), "r"(a[3]),
          "r"(b[0]), "r"(b[1]));
}

__device__ __forceinline__ void ldsm_x4(uint32_t& r0, uint32_t& r1, uint32_t& r2, uint32_t& r3,
                                        uint32_t addr) {
    asm volatile("ldmatrix.sync.aligned.m8n8.x4.shared.b16 {%0,%1,%2,%3}, [%4];"
        : "=r"(r0), "=r"(r1), "=r"(r2), "=r"(r3) : "r"(addr));
}

__device__ __forceinline__ void cp16(uint32_t dst, const void* src) {
    asm volatile("cp.async.cg.shared.global [%0], [%1], 16;" :: "r"(dst), "l"(src));
}
__device__ __forceinline__ void cp_commit() {
    asm volatile("cp.async.commit_group;" ::: "memory");
}
template<int N>
__device__ __forceinline__ void cp_wait() {
    asm volatile("cp.async.wait_group %0;" :: "n"(N) : "memory");
}

__device__ __forceinline__ float sigm(float x) { return 1.f/(1.f + expf(-x)); }

__device__ __forceinline__ uint32_t swz(int row, int ch) {
    return (uint32_t)(row * 128 + ((ch ^ (row & 7)) << 4));
}

// ---------------- conversions -----------------------------------------------
__device__ __forceinline__ void store_blk(__nv_bfloat16* dst, int c4, float4 v) {
    uint32_t h0, l0, h1, l1;
    split2(v.x, v.y, h0, l0);
    split2(v.z, v.w, h1, l1);
    __nv_bfloat16* base = dst + ((c4 >> 5) * 64) + (c4 & 31);
    *(uint32_t*)(base)      = h0; *(uint32_t*)(base + 2)  = h1;
    *(uint32_t*)(base + 32) = l0; *(uint32_t*)(base + 34) = l1;
}

__global__ void __launch_bounds__(256)
conv_acts(const float4* __restrict__ inA, __nv_bfloat16* __restrict__ dA,
          const float4* __restrict__ inB, __nv_bfloat16* __restrict__ dB)
{
    int i = blockIdx.x * blockDim.x + threadIdx.x;
    int n4 = ROWS * 64;
    const float4* src; __nv_bfloat16* dst; int j;
    if (i < n4) { src = inA; dst = dA; j = i; }
    else if (i < 2 * n4) { src = inB; dst = dB; j = i - n4; }
    else return;
    int r = j >> 6, c4 = (j & 63) << 2;
    store_blk(dst + (size_t)r * 512, c4, src[j]);
}

__global__ void __launch_bounds__(256)
conv_wts(const float* __restrict__ fc1w, const float* __restrict__ wih,
         const float* __restrict__ whh, const float* __restrict__ qw,
         const float* __restrict__ kw, const float* __restrict__ vw,
         __nv_bfloat16* __restrict__ W1, __nv_bfloat16* __restrict__ Wi,
         __nv_bfloat16* __restrict__ Wh, __nv_bfloat16* __restrict__ QKV)
{
    int i = blockIdx.x * blockDim.x + threadIdx.x;
    if (i >= 1984 * 64) return;
    int row = i >> 6, c4 = (i & 63) << 2;
    const float* src; __nv_bfloat16* dst;
    if (row < 256)       { src = fc1w + (size_t)row * 256;        dst = W1 + (size_t)row * 512; }
    else if (row < 1024) { int r = row - 256;  src = wih + (size_t)r * 256; dst = Wi + (size_t)r * 512; }
    else if (row < 1792) { int r = row - 1024; src = whh + (size_t)r * 256; dst = Wh + (size_t)r * 512; }
    else {
        int r = row - 1792;
        src = (r < 64) ? (qw + (size_t)r * 256)
            : (r < 128) ? (kw + (size_t)(r - 64) * 256)
                        : (vw + (size_t)(r - 128) * 256);
        dst = QKV + (size_t)r * 512;
    }
    store_blk(dst, c4, *(const float4*)(src + c4));
}

__global__ void __launch_bounds__(256)
conv_p1w(const float4* __restrict__ src, __nv_bfloat16* __restrict__ dst)
{
    int i = blockIdx.x * blockDim.x + threadIdx.x;
    if (i >= 256 * 80) return;
    int r = i / 80, c4 = (i - r * 80) << 2;
    store_blk(dst + (size_t)r * 640, c4, src[i]);
}

// ================= generic GEMM: 128x64 tile, cp.async 3-stage ==============
#define GST_B 24576
#define GW_OFF 16384

template<int ACT, int OUTHL>
__global__ void __launch_bounds__(256,2)
gemmHL(const __nv_bfloat16* __restrict__ A, int as,
       const __nv_bfloat16* __restrict__ W, int ws,
       const float* __restrict__ bias,
       float* __restrict__ Cf, int ldc,
       __nv_bfloat16* __restrict__ Chl, int os,
       int ntiles)
{
    extern __shared__ char smc[];
    const uint32_t smb = (uint32_t)__cvta_generic_to_shared(smc);
    const int tid = threadIdx.x, lane = tid & 31, warp = tid >> 5;
    const int group = lane >> 2, tig = lane & 3;
    const int wm = warp >> 1, wn = warp & 1;
    const int m0 = blockIdx.y * 128, n0 = blockIdx.x * 64;

    const int arow = (lane & 7) + ((lane >> 3) & 1) * 8;
    const int akc  = (lane >> 4) & 1;
    const int brow = (lane & 7) + ((lane >> 4) & 1) * 8;
    const int bkc  = (lane >> 3) & 1;

    float acc[2][4][4];
    #pragma unroll
    for (int mi = 0; mi < 2; mi++)
        #pragma unroll
        for (int ni = 0; ni < 4; ni++)
            #pragma unroll
            for (int j = 0; j < 4; j++) acc[mi][ni][j] = 0.f;

    const int lrow = tid >> 3, lch = tid & 7;

    #define G_ISSUE(t) {                                                        \
        uint32_t sb_ = smb + ((t) % 3) * GST_B;                                 \
        _Pragma("unroll")                                                       \
        for (int i_ = 0; i_ < 4; i_++) {                                        \
            int row_ = lrow + i_ * 32;                                          \
            cp16(sb_ + swz(row_, lch),                                          \
                 A + (size_t)(m0 + row_) * as + (t) * 64 + lch * 8);            \
        }                                                                       \
        _Pragma("unroll")                                                       \
        for (int i_ = 0; i_ < 2; i_++) {                                        \
            int row_ = lrow + i_ * 32;                                          \
            cp16(sb_ + GW_OFF + swz(row_, lch),                                 \
                 W + (size_t)(n0 + row_) * ws + (t) * 64 + lch * 8);            \
        }                                                                       \
        cp_commit();                                                            \
    }

    G_ISSUE(0);
    if (ntiles > 1) G_ISSUE(1);

    for (int t = 0; t < ntiles; t++) {
        if (t + 1 < ntiles) cp_wait<1>(); else cp_wait<0>();
        __syncthreads();
        if (t + 2 < ntiles) G_ISSUE(t + 2);

        const uint32_t sb = smb + (t % 3) * GST_B;
        #pragma unroll
        for (int kk = 0; kk < 2; kk++) {
            uint32_t aH[2][4], aL[2][4];
            #pragma unroll
            for (int mi = 0; mi < 2; mi++) {
                int r = wm * 32 + mi * 16 + arow;
                int ch = 2 * kk + akc;
                ldsm_x4(aH[mi][0], aH[mi][1], aH[mi][2], aH[mi][3], sb + swz(r, ch));
                ldsm_x4(aL[mi][0], aL[mi][1], aL[mi][2], aL[mi][3], sb + swz(r, ch + 4));
            }
            #pragma unroll
            for (int j = 0; j < 2; j++) {
                int r = wn * 32 + j * 16 + brow;
                int ch = 2 * kk + bkc;
                uint32_t bH[2][2], bL[2][2];
                ldsm_x4(bH[0][0], bH[0][1], bH[1][0], bH[1][1], sb + GW_OFF + swz(r, ch));
                ldsm_x4(bL[0][0], bL[0][1], bL[1][0], bL[1][1], sb + GW_OFF + swz(r, ch + 4));
                #pragma unroll
                for (int mi = 0; mi < 2; mi++)
                    #pragma unroll
                    for (int p = 0; p < 2; p++) {
                        int ni = 2 * j + p;
                        mma_bf16(acc[mi][ni], aH[mi], bL[p]);
                        mma_bf16(acc[mi][ni], aL[mi], bH[p]);
                        mma_bf16(acc[mi][ni], aH[mi], bH[p]);
                    }
            }
        }
    }
    #undef G_ISSUE

    #pragma unroll
    for (int mi = 0; mi < 2; mi++) {
        #pragma unroll
        for (int ni = 0; ni < 4; ni++) {
            int row = m0 + wm * 32 + mi * 16 + group;
            int col = n0 + wn * 32 + ni * 8 + 2 * tig;
            float b0 = bias[col], b1 = bias[col + 1];
            float v0 = acc[mi][ni][0] + b0;
            float v1 = acc[mi][ni][1] + b1;
            float v2 = acc[mi][ni][2] + b0;
            float v3 = acc[mi][ni][3] + b1;
            if (ACT == 1) {
                v0 = fmaxf(v0, 0.f); v1 = fmaxf(v1, 0.f);
                v2 = fmaxf(v2, 0.f); v3 = fmaxf(v3, 0.f);
            }
            if (OUTHL == 0) {
                *(float2*)(Cf + (size_t)row * ldc + col)       = make_float2(v0, v1);
                *(float2*)(Cf + (size_t)(row + 8) * ldc + col) = make_float2(v2, v3);
            } else {
                int b = col >> 5, pos = col & 31;
                uint32_t h, l;
                split2(v0, v1, h, l);
                *(uint32_t*)(Chl + (size_t)row * os + b * 64 + pos)      = h;
                *(uint32_t*)(Chl + (size_t)row * os + b * 64 + 32 + pos) = l;
                split2(v2, v3, h, l);
                *(uint32_t*)(Chl + (size_t)(row + 8) * os + b * 64 + pos)      = h;
                *(uint32_t*)(Chl + (size_t)(row + 8) * os + b * 64 + 32 + pos) = l;
            }
        }
    }
}

// ================= gru_fused (R8 structure): gh GEMM 64x192 + GRU ==========
#define FST_B 32768
#define FW_OFF 8192
#define STG_STRIDE 196

__global__ void __launch_bounds__(256,2)
gru_fused(const __nv_bfloat16* __restrict__ HidHL, const __nv_bfloat16* __restrict__ WhHL,
          const float* __restrict__ hidden,
          const float* __restrict__ bhh, const float* __restrict__ GI,
          __nv_bfloat16* __restrict__ cchl, float* __restrict__ hout)
{
    extern __shared__ char smc[];
    const uint32_t smb = (uint32_t)__cvta_generic_to_shared(smc);
    float* stage = (float*)smc;

    const int tid = threadIdx.x, lane = tid & 31, warp = tid >> 5;
    const int group = lane >> 2, tig = lane & 3;
    const int wm = warp >> 2, wn = warp & 3;
    const int m0 = blockIdx.y * 64, n0h = blockIdx.x * 64;

    const int arow = (lane & 7) + ((lane >> 3) & 1) * 8;
    const int akc  = (lane >> 4) & 1;
    const int brow = (lane & 7) + ((lane >> 4) & 1) * 8;
    const int bkc  = (lane >> 3) & 1;
    const int lrow = tid >> 3, lch = tid & 7;

    float acc[2][6][4];
    #pragma unroll
    for (int mi = 0; mi < 2; mi++)
        #pragma unroll
        for (int ni = 0; ni < 6; ni++)
            #pragma unroll
            for (int j = 0; j < 4; j++) acc[mi][ni][j] = 0.f;

    #define F_ISSUE(t) {                                                        \
        uint32_t sb_ = smb + ((t) % 3) * FST_B;                                 \
        _Pragma("unroll")                                                       \
        for (int i_ = 0; i_ < 2; i_++) {                                        \
            int row_ = lrow + i_ * 32;                                          \
            cp16(sb_ + swz(row_, lch),                                          \
                 HidHL + (size_t)(m0 + row_) * 512 + (t) * 64 + lch * 8);       \
        }                                                                       \
        _Pragma("unroll")                                                       \
        for (int i_ = 0; i_ < 6; i_++) {                                        \
            int row_ = lrow + i_ * 32;                                          \
            int wr_ = (row_ >> 6) * 256 + n0h + (row_ & 63);                    \
            cp16(sb_ + FW_OFF + swz(row_, lch),                                 \
                 WhHL + (size_t)wr_ * 512 + (t) * 64 + lch * 8);                \
        }                                                                       \
        cp_commit();                                                            \
    }

    F_ISSUE(0); F_ISSUE(1);

    for (int t = 0; t < 8; t++) {
        if (t + 1 < 8) cp_wait<1>(); else cp_wait<0>();
        __syncthreads();
        if (t + 2 < 8) F_ISSUE(t + 2);

        const uint32_t sb = smb + (t % 3) * FST_B;
        #pragma unroll
        for (int kk = 0; kk < 2; kk++) {
            uint32_t aH[2][4], aL[2][4];
            #pragma unroll
            for (int mi = 0; mi < 2; mi++) {
                int r = wm * 32 + mi * 16 + arow;
                int ch = 2 * kk + akc;
                ldsm_x4(aH[mi][0], aH[mi][1], aH[mi][2], aH[mi][3], sb + swz(r, ch));
                ldsm_x4(aL[mi][0], aL[mi][1], aL[mi][2], aL[mi][3], sb + swz(r, ch + 4));
            }
            #pragma unroll
            for (int j = 0; j < 3; j++) {
                int r = wn * 48 + j * 16 + brow;
                int ch = 2 * kk + bkc;
                uint32_t bH[2][2], bL[2][2];
                ldsm_x4(bH[0][0], bH[0][1], bH[1][0], bH[1][1], sb + FW_OFF + swz(r, ch));
                ldsm_x4(bL[0][0], bL[0][1], bL[1][0], bL[1][1], sb + FW_OFF + swz(r, ch + 4));
                #pragma unroll
                for (int mi = 0; mi < 2; mi++)
                    #pragma unroll
                    for (int p = 0; p < 2; p++) {
                        int ni = 2 * j + p;
                        mma_bf16(acc[mi][ni], aH[mi], bL[p]);
                        mma_bf16(acc[mi][ni], aL[mi], bH[p]);
                        mma_bf16(acc[mi][ni], aH[mi], bH[p]);
                    }
            }
        }
    }
    #undef F_ISSUE
    __syncthreads();

    #pragma unroll
    for (int mi = 0; mi < 2; mi++) {
        #pragma unroll
        for (int ni = 0; ni < 6; ni++) {
            int row = wm * 32 + mi * 16 + group;
            int col = wn * 48 + ni * 8 + 2 * tig;
            stage[row * STG_STRIDE + col]         = acc[mi][ni][0];
            stage[row * STG_STRIDE + col + 1]     = acc[mi][ni][1];
            stage[(row+8) * STG_STRIDE + col]     = acc[mi][ni][2];
            stage[(row+8) * STG_STRIDE + col + 1] = acc[mi][ni][3];
        }
    }
    __syncthreads();

    #pragma unroll
    for (int j = 0; j < 16; j++) {
        int e = tid + j * 256;
        int row = e >> 6, hcol = e & 63;
        int grow = m0 + row;
        int gcol = n0h + hcol;
        float ghr = stage[row * STG_STRIDE + hcol]       + bhh[gcol];
        float ghz = stage[row * STG_STRIDE + 64 + hcol]  + bhh[256 + gcol];
        float ghn = stage[row * STG_STRIDE + 128 + hcol] + bhh[512 + gcol];
        const float* gi = GI + (size_t)grow * 768 + gcol;
        float gir = gi[0], giz = gi[256], gin = gi[512];
        float hin = hidden[(size_t)grow * 256 + gcol];
        float r = sigm(gir + ghr);
        float z = sigm(giz + ghz);
        float n = tanhf(gin + r * ghn);
        float h = (1.f - z) * n + z * hin;
        int b = gcol >> 5, pos = gcol & 31;
        __nv_bfloat16 hb = __float2bfloat16_rn(h);
        __nv_bfloat16 lb = __float2bfloat16_rn(h - __bfloat162float(hb));
        __nv_bfloat16* dp = cchl + (size_t)grow * 640 + b * 64 + pos;
        dp[0]  = hb;
        dp[32] = lb;
        if (hout) hout[(size_t)grow * 256 + gcol] = h;
    }
}

// ================= fused q/k/v GEMM + per-batch sparse attention ============
// CTA = 64 rows = 2 batch elements. GEMM mainloop as before; epilogue stages
// Q/K/V in smem, runs scores/top-8/softmax/messages, writes gated output.
__global__ void __launch_bounds__(256,2)
qkv_attn(const __nv_bfloat16* __restrict__ CChl, const __nv_bfloat16* __restrict__ QKVw,
         const float* __restrict__ qb, const float* __restrict__ kb,
         const float* __restrict__ vb, const float* __restrict__ gate,
         __nv_bfloat16* __restrict__ cchl_out)
{
    extern __shared__ char smc[];
    const uint32_t smb = (uint32_t)__cvta_generic_to_shared(smc);

    const int tid = threadIdx.x, lane = tid & 31, warp = tid >> 5;
    const int group = lane >> 2, tig = lane & 3;
    const int wm = warp >> 2, wn = warp & 3;
    const int m0 = blockIdx.y * 64;

    const int arow = (lane & 7) + ((lane >> 3) & 1) * 8;
    const int akc  = (lane >> 4) & 1;
    const int brow = (lane & 7) + ((lane >> 4) & 1) * 8;
    const int bkc  = (lane >> 3) & 1;
    const int lrow = tid >> 3, lch = tid & 7;

    float acc[2][6][4];
    #pragma unroll
    for (int mi = 0; mi < 2; mi++)
        #pragma unroll
        for (int ni = 0; ni < 6; ni++)
            #pragma unroll
            for (int j = 0; j < 4; j++) acc[mi][ni][j] = 0.f;

    #define Q_ISSUE(t) {                                                        \
        uint32_t sb_ = smb + ((t) % 3) * FST_B;                                 \
        _Pragma("unroll")                                                       \
        for (int i_ = 0; i_ < 2; i_++) {                                        \
            int row_ = lrow + i_ * 32;                                          \
            cp16(sb_ + swz(row_, lch),                                          \
                 CChl + (size_t)(m0 + row_) * 640 + (t) * 64 + lch * 8);        \
        }                                                                       \
        _Pragma("unroll")                                                       \
        for (int i_ = 0; i_ < 6; i_++) {                                        \
            int row_ = lrow + i_ * 32;                                          \
            cp16(sb_ + FW_OFF + swz(row_, lch),                                 \
                 QKVw + (size_t)row_ * 512 + (t) * 64 + lch * 8);               \
        }                                                                       \
        cp_commit();                                                            \
    }

    Q_ISSUE(0); Q_ISSUE(1);

    for (int t = 0; t < 8; t++) {
        if (t + 1 < 8) cp_wait<1>(); else cp_wait<0>();
        __syncthreads();
        if (t + 2 < 8) Q_ISSUE(t + 2);

        const uint32_t sb = smb + (t % 3) * FST_B;
        #pragma unroll
        for (int kk = 0; kk < 2; kk++) {
            uint32_t aH[2][4], aL[2][4];
            #pragma unroll
            for (int mi = 0; mi < 2; mi++) {
                int r = wm * 32 + mi * 16 + arow;
                int ch = 2 * kk + akc;
                ldsm_x4(aH[mi][0], aH[mi][1], aH[mi][2], aH[mi][3], sb + swz(r, ch));
                ldsm_x4(aL[mi][0], aL[mi][1], aL[mi][2], aL[mi][3], sb + swz(r, ch + 4));
            }
            #pragma unroll
            for (int j = 0; j < 3; j++) {
                int r = wn * 48 + j * 16 + brow;
                int ch = 2 * kk + bkc;
                uint32_t bH[2][2], bL[2][2];
                ldsm_x4(bH[0][0], bH[0][1], bH[1][0], bH[1][1], sb + FW_OFF + swz(r, ch));
                ldsm_x4(bL[0][0], bL[0][1], bL[1][0], bL[1][1], sb + FW_OFF + swz(r, ch + 4));
                #pragma unroll
                for (int mi = 0; mi < 2; mi++)
                    #pragma unroll
                    for (int p = 0; p < 2; p++) {
                        int ni = 2 * j + p;
                        mma_bf16(acc[mi][ni], aH[mi], bL[p]);
                        mma_bf16(acc[mi][ni], aL[mi], bH[p]);
                        mma_bf16(acc[mi][ni], aH[mi], bH[p]);
                    }
            }
        }
    }
    #undef Q_ISSUE

    // ---- stage Q/K/V (bias applied) in smem ----
    __syncthreads();
    float* QS = (float*)smc;            // [64][65]
    float* KS = QS + 64*65;
    float* VS = KS + 64*65;
    float* SS = VS + 64*65;             // [8][32*33]  (2 batches x 4 heads)

    #pragma unroll
    for (int mi = 0; mi < 2; mi++) {
        #pragma unroll
        for (int ni = 0; ni < 6; ni++) {
            int row = wm * 32 + mi * 16 + group;
            int col = wn * 48 + ni * 8 + 2 * tig;
            float* dst; const float* bs; int oc;
            if (col < 64)       { dst = QS; bs = qb; oc = col; }
            else if (col < 128) { dst = KS; bs = kb; oc = col - 64; }
            else                { dst = VS; bs = vb; oc = col - 128; }
            float b0 = bs[oc], b1 = bs[oc + 1];
            dst[row * 65 + oc]           = acc[mi][ni][0] + b0;
            dst[row * 65 + oc + 1]       = acc[mi][ni][1] + b1;
            dst[(row + 8) * 65 + oc]     = acc[mi][ni][2] + b0;
            dst[(row + 8) * 65 + oc + 1] = acc[mi][ni][3] + b1;
        }
    }
    __syncthreads();

    // ---- scores (2 batches x 4 heads x 32 q x 32 k) ----
    for (int i = tid; i < 8192; i += 256) {
        int b2 = i >> 12, rem = i & 4095;
        int q = rem >> 7, hk = rem & 127;
        int h = hk >> 5, k = hk & 31;
        float s;
        if (q == k) s = NEGV;
        else {
            const float* qp = QS + (b2 * 32 + q) * 65 + h * 16;
            const float* kp = KS + (b2 * 32 + k) * 65 + h * 16;
            float a = 0.f;
            #pragma unroll
            for (int d = 0; d < 16; d++) a += qp[d] * kp[d];
            s = 0.25f * a;
        }
        SS[(b2 * 4 + h) * 1056 + q * 33 + k] = s;
    }
    __syncthreads();

    // ---- top-8 + softmax (256 = 2 x 4 x 32 rows) ----
    {
        int b2 = tid >> 7, h = (tid >> 5) & 3, q = tid & 31;
        float* sp = SS + (b2 * 4 + h) * 1056 + q * 33;
        float v[32];
        #pragma unroll
        for (int k = 0; k < 32; k++) v[k] = sp[k];
        float maxv = -INFINITY;
        unsigned keep = 0u;
        #pragma unroll
        for (int k = 0; k < 32; k++) {
            int cnt = 0;
            #pragma unroll
            for (int j = 0; j < 32; j++) cnt += (v[j] > v[k]);
            if (cnt < TOPKN) { keep |= (1u << k); maxv = fmaxf(maxv, v[k]); }
        }
        float e[32], sum = 0.f;
        #pragma unroll
        for (int k = 0; k < 32; k++) {
            float ek = ((keep >> k) & 1u) ? expf(v[k] - maxv) : 0.f;
            e[k] = ek; sum += ek;
        }
        float inv = 1.f / sum;
        #pragma unroll
        for (int k = 0; k < 32; k++) sp[k] = e[k] * inv;
    }
    __syncthreads();

    // ---- messages * gates -> CCHL blocks 8-9 ----
    for (int i = tid; i < 4096; i += 256) {
        int b2 = i >> 11, rem = i & 2047;
        int q = rem >> 6, hv = rem & 63, h = hv >> 4;
        const float* sp = SS + (b2 * 4 + h) * 1056 + q * 33;
        const float* vp = VS + (b2 * 32) * 65 + hv;
        float a = 0.f;
        #pragma unroll
        for (int k = 0; k < 32; k++) a += sp[k] * vp[k * 65];
        int grow = m0 + b2 * 32 + q;
        float gt = gate[(size_t)grow * NHEAD + h];
        float g = a * gt;
        int c = 256 + hv;
        int blk = c >> 5, pos = c & 31;
        __nv_bfloat16 hb = __float2bfloat16_rn(g);
        __nv_bfloat16 lb = __float2bfloat16_rn(g - __bfloat162float(hb));
        __nv_bfloat16* dp = cchl_out + (size_t)grow * 640 + blk * 64 + pos;
        dp[0]  = hb;
        dp[32] = lb;
    }
}

// ---------------- head gates ------------------------------------------------
__global__ void __launch_bounds__(256)
gate_kernel(const __nv_bfloat16* __restrict__ CChl, const float* __restrict__ gw,
            const float* __restrict__ gb, float* __restrict__ gate)
{
    int gwp  = (int)(((size_t)blockIdx.x*blockDim.x + threadIdx.x) >> 5);
    int lane = threadIdx.x & 31;
    if (gwp >= ROWS) return;
    int o = lane >> 3, part = lane & 7;
    const __nv_bfloat16* hr = CChl + (size_t)gwp * 640;
    const float* wr = gw + o * 256;
    float s = 0.f;
    #pragma unroll
    for (int j = 0; j < 8; j++) {
        int k = part * 4 + 32 * j;
        uint32_t h0 = *(const uint32_t*)(hr + j * 64 + part * 4);
        uint32_t h1 = *(const uint32_t*)(hr + j * 64 + part * 4 + 2);
        uint32_t l0 = *(const uint32_t*)(hr + j * 64 + 32 + part * 4);
        uint32_t l1 = *(const uint32_t*)(hr + j * 64 + 32 + part * 4 + 2);
        float2 a = rec2(h0, l0), b = rec2(h1, l1);
        float4 wv = *(const float4*)(wr + k);
        s += a.x*wv.x + a.y*wv.y + b.x*wv.z + b.y*wv.w;
    }
    s += __shfl_down_sync(0xffffffffu, s, 4, 8);
    s += __shfl_down_sync(0xffffffffu, s, 2, 8);
    s += __shfl_down_sync(0xffffffffu, s, 1, 8);
    if (part == 0) gate[(size_t)gwp*NHEAD + o] = sigm(s + gb[o]);
}

// ---------------- p2 head ---------------------------------------------------
__global__ void __launch_bounds__(256)
p2_kernel(const float* __restrict__ P1, const float* __restrict__ w,
          const float* __restrict__ b, float* __restrict__ out)
{
    __shared__ float WS[20*257];
    int tid = threadIdx.x;
    for (int i = tid; i < 20*256; i += 256) {
        int o = i >> 8, k = i & 255;
        WS[o*257 + k] = w[i];
    }
    __syncthreads();
    int r = tid / 20, o = tid % 20;
    int row = blockIdx.x*12 + r;
    if (tid >= 240 || row >= ROWS) return;
    const float* a  = P1 + (size_t)row*256;
    const float* wr = WS + o*257;
    float s = b[o];
    #pragma unroll 4
    for (int k = 0; k < 256; k += 4) {
        float4 av = *(const float4*)(a + k);
        s += av.x*wr[k] + av.y*wr[k+1] + av.z*wr[k+2] + av.w*wr[k+3];
    }
    out[(size_t)row*NACT + o] = s;
}

// ---------------------------------------------------------------------------
extern "C" void kernel_launch(void* const* d_in, const int* in_sizes, int n_in,
                              void* d_out, int out_size)
{
    const float* inputs = (const float*)d_in[0];
    const float* hidden = (const float*)d_in[1];
    const float* fc1_w  = (const float*)d_in[2];
    const float* fc1_b  = (const float*)d_in[3];
    const float* w_ih   = (const float*)d_in[4];
    const float* w_hh   = (const float*)d_in[5];
    const float* b_ih   = (const float*)d_in[6];
    const float* b_hh   = (const float*)d_in[7];
    const float* q_w    = (const float*)d_in[8];
    const float* q_b    = (const float*)d_in[9];
    const float* k_w    = (const float*)d_in[10];
    const float* k_b    = (const float*)d_in[11];
    const float* v_w    = (const float*)d_in[12];
    const float* v_b    = (const float*)d_in[13];
    const float* g_w    = (const float*)d_in[14];
    const float* g_b    = (const float*)d_in[15];
    const float* p1_w   = (const float*)d_in[16];
    const float* p1_b   = (const float*)d_in[17];
    const float* p2_w   = (const float*)d_in[18];
    const float* p2_b   = (const float*)d_in[19];

    float *GI, *GT, *P1;
    __nv_bfloat16 *InHL, *HidHL, *XHL, *CCHL, *W1HL, *WiHL, *WhHL, *QKVHL, *P1WHL;
    cudaGetSymbolAddress((void**)&GI, g_GI);
    cudaGetSymbolAddress((void**)&GT, g_GT);
    cudaGetSymbolAddress((void**)&P1, g_P1);
    cudaGetSymbolAddress((void**)&InHL,  g_InHL);
    cudaGetSymbolAddress((void**)&HidHL, g_HidHL);
    cudaGetSymbolAddress((void**)&XHL,   g_XHL);
    cudaGetSymbolAddress((void**)&CCHL,  g_CCHL);
    cudaGetSymbolAddress((void**)&W1HL,  g_W1HL);
    cudaGetSymbolAddress((void**)&WiHL,  g_WiHL);
    cudaGetSymbolAddress((void**)&WhHL,  g_WhHL);
    cudaGetSymbolAddress((void**)&QKVHL, g_QKVHL);
    cudaGetSymbolAddress((void**)&P1WHL, g_P1WHL);

    float* out  = (float*)d_out;
    float* hout = nullptr;
    long long need = (long long)ROWS*NACT + (long long)ROWS*HIDN;
    if ((long long)out_size >= need) hout = out + (size_t)ROWS*NACT;

    const int gsm  = 3 * GST_B;   // 73728
    const int fsm  = 3 * FST_B;   // 98304
    static int smem_set = 0;
    if (!smem_set) {
        cudaFuncSetAttribute(gemmHL<0,0>, cudaFuncAttributeMaxDynamicSharedMemorySize, gsm);
        cudaFuncSetAttribute(gemmHL<1,0>, cudaFuncAttributeMaxDynamicSharedMemorySize, gsm);
        cudaFuncSetAttribute(gemmHL<1,1>, cudaFuncAttributeMaxDynamicSharedMemorySize, gsm);
        cudaFuncSetAttribute(gru_fused, cudaFuncAttributeMaxDynamicSharedMemorySize, fsm);
        cudaFuncSetAttribute(qkv_attn, cudaFuncAttributeMaxDynamicSharedMemorySize, fsm);
        smem_set = 1;
    }

    dim3 thr(256);

    // 0) conversions (3 launches)
    conv_acts<<<(2*ROWS*64 + 255)/256, thr>>>((const float4*)inputs, InHL,
                                              (const float4*)hidden, HidHL);
    conv_wts<<<(1984*64 + 255)/256, thr>>>(fc1_w, w_ih, w_hh, q_w, k_w, v_w,
                                           W1HL, WiHL, WhHL, QKVHL);
    conv_p1w<<<(256*80 + 255)/256, thr>>>((const float4*)p1_w, P1WHL);

    // 1) x = relu(inputs @ fc1_w^T + fc1_b) -> XHL
    gemmHL<1,1><<<dim3(4, ROWS/128), thr, gsm>>>(InHL, 512, W1HL, 512, fc1_b,
                                                 nullptr, 0, XHL, 512, 8);
    // 2) gi = x @ W_ih^T + b_ih -> GI (f32)
    gemmHL<0,0><<<dim3(12, ROWS/128), thr, gsm>>>(XHL, 512, WiHL, 512, b_ih,
                                                  GI, 768, nullptr, 0, 8);
    // 3) fused gh GEMM + GRU -> CCHL blocks 0-7 + hout
    gru_fused<<<dim3(4, ROWS/64), thr, fsm>>>(HidHL, WhHL, hidden, b_hh, GI, CCHL, hout);
    // 4) head gates (before attention; needs only CCHL h-part)
    gate_kernel<<<(ROWS*32)/256, thr>>>(CCHL, g_w, g_b, GT);
    // 5) fused q/k/v GEMM + sparse attention -> CCHL blocks 8-9
    qkv_attn<<<dim3(1, ROWS/64), thr, fsm>>>(CCHL, QKVHL, q_b, k_b, v_b, GT, CCHL);
    // 6) p1 = relu(CC @ p1_w^T + p1_b) -> P1 (f32)
    gemmHL<1,0><<<dim3(4, ROWS/128), thr, gsm>>>(CCHL, 640, P1WHL, 640, p1_b,
                                                 P1, 256, nullptr, 0, 10);
    // 7) logits
    p2_kernel<<<(ROWS + 11)/12, thr>>>(P1, p2_w, p2_b, out);
}

// round 11
// speedup vs baseline: 1.0632x; 1.0299x over previous
#include <cuda_runtime.h>
#include <cuda_bf16.h>
#include <math.h>
#include <stdint.h>

#define BSZ    2048
#define A_N    32
#define ROWS   (BSZ*A_N)        // 65536
#define HIDN   256
#define NHEAD  4
#define TOPKN  8
#define NACT   20
#define NEGV   (-1e10f)

// ---------------- scratch ---------------------------------------------------
__device__ __nv_bfloat16 g_InHL [(size_t)ROWS*512];
__device__ __nv_bfloat16 g_HidHL[(size_t)ROWS*512];
__device__ __nv_bfloat16 g_XHL  [(size_t)ROWS*512];
__device__ __nv_bfloat16 g_CCHL [(size_t)ROWS*640];
__device__ __nv_bfloat16 g_W1HL [256*512];
__device__ __nv_bfloat16 g_WiHL [768*512];
__device__ __nv_bfloat16 g_WhHL [768*512];
__device__ __nv_bfloat16 g_QKVHL[192*512];
__device__ __nv_bfloat16 g_P1WHL[256*640];
__device__ float g_GI[(size_t)ROWS*3*HIDN];
__device__ float g_GT[(size_t)ROWS*NHEAD];
__device__ float g_P1[(size_t)ROWS*HIDN];

// ---------------- helpers ---------------------------------------------------
__device__ __forceinline__ void split2(float x0, float x1, uint32_t& wh, uint32_t& wl) {
    __nv_bfloat16 h0 = __float2bfloat16_rn(x0);
    __nv_bfloat16 h1 = __float2bfloat16_rn(x1);
    __nv_bfloat16 l0 = __float2bfloat16_rn(x0 - __bfloat162float(h0));
    __nv_bfloat16 l1 = __float2bfloat16_rn(x1 - __bfloat162float(h1));
    __nv_bfloat162 H = __nv_bfloat162(h0, h1);
    __nv_bfloat162 L = __nv_bfloat162(l0, l1);
    wh = *reinterpret_cast<uint32_t*>(&H);
    wl = *reinterpret_cast<uint32_t*>(&L);
}

__device__ __forceinline__ float2 rec2(uint32_t h, uint32_t l) {
    __nv_bfloat162 H = *reinterpret_cast<__nv_bfloat162*>(&h);
    __nv_bfloat162 L = *reinterpret_cast<__nv_bfloat162*>(&l);
    return make_float2(__bfloat162float(H.x) + __bfloat162float(L.x),
                       __bfloat162float(H.y) + __bfloat162float(L.y));
}

__device__ __forceinline__ void mma_bf16(float* d, const uint32_t* a, const uint32_t* b) {
    asm volatile(
        "mma.sync.aligned.m16n8k16.row.col.f32.bf16.bf16.f32 "
        "{%0,%1,%2,%3}, {%4,%5,%6,%7}, {%8,%9}, {%0,%1,%2,%3};"
        : "+f"(d[0]), "+f"(d[1]), "+f"(d[2]), "+f"(d[3])
        : "r"(a[0]), "r"(a[1]), "r"(a[2]), "r"(a[3]),
          "r"(b[0]), "r"(b[1]));
}

__device__ __forceinline__ void ldsm_x4(uint32_t& r0, uint32_t& r1, uint32_t& r2, uint32_t& r3,
                                        uint32_t addr) {
    asm volatile("ldmatrix.sync.aligned.m8n8.x4.shared.b16 {%0,%1,%2,%3}, [%4];"
        : "=r"(r0), "=r"(r1), "=r"(r2), "=r"(r3) : "r"(addr));
}

__device__ __forceinline__ void cp16(uint32_t dst, const void* src) {
    asm volatile("cp.async.cg.shared.global [%0], [%1], 16;" :: "r"(dst), "l"(src));
}
__device__ __forceinline__ void cp_commit() {
    asm volatile("cp.async.commit_group;" ::: "memory");
}
template<int N>
__device__ __forceinline__ void cp_wait() {
    asm volatile("cp.async.wait_group %0;" :: "n"(N) : "memory");
}

__device__ __forceinline__ float sigm(float x) { return 1.f/(1.f + expf(-x)); }

__device__ __forceinline__ uint32_t swz(int row, int ch) {
    return (uint32_t)(row * 128 + ((ch ^ (row & 7)) << 4));
}

// ---------------- conversions -----------------------------------------------
__device__ __forceinline__ void store_blk(__nv_bfloat16* dst, int c4, float4 v) {
    uint32_t h0, l0, h1, l1;
    split2(v.x, v.y, h0, l0);
    split2(v.z, v.w, h1, l1);
    __nv_bfloat16* base = dst + ((c4 >> 5) * 64) + (c4 & 31);
    *(uint32_t*)(base)      = h0; *(uint32_t*)(base + 2)  = h1;
    *(uint32_t*)(base + 32) = l0; *(uint32_t*)(base + 34) = l1;
}

__global__ void __launch_bounds__(256)
conv_acts(const float4* __restrict__ inA, __nv_bfloat16* __restrict__ dA,
          const float4* __restrict__ inB, __nv_bfloat16* __restrict__ dB)
{
    int i = blockIdx.x * blockDim.x + threadIdx.x;
    int n4 = ROWS * 64;
    const float4* src; __nv_bfloat16* dst; int j;
    if (i < n4) { src = inA; dst = dA; j = i; }
    else if (i < 2 * n4) { src = inB; dst = dB; j = i - n4; }
    else return;
    int r = j >> 6, c4 = (j & 63) << 2;
    store_blk(dst + (size_t)r * 512, c4, src[j]);
}

__global__ void __launch_bounds__(256)
conv_wts(const float* __restrict__ fc1w, const float* __restrict__ wih,
         const float* __restrict__ whh, const float* __restrict__ qw,
         const float* __restrict__ kw, const float* __restrict__ vw,
         __nv_bfloat16* __restrict__ W1, __nv_bfloat16* __restrict__ Wi,
         __nv_bfloat16* __restrict__ Wh, __nv_bfloat16* __restrict__ QKV)
{
    int i = blockIdx.x * blockDim.x + threadIdx.x;
    if (i >= 1984 * 64) return;
    int row = i >> 6, c4 = (i & 63) << 2;
    const float* src; __nv_bfloat16* dst;
    if (row < 256)       { src = fc1w + (size_t)row * 256;        dst = W1 + (size_t)row * 512; }
    else if (row < 1024) { int r = row - 256;  src = wih + (size_t)r * 256; dst = Wi + (size_t)r * 512; }
    else if (row < 1792) { int r = row - 1024; src = whh + (size_t)r * 256; dst = Wh + (size_t)r * 512; }
    else {
        int r = row - 1792;
        src = (r < 64) ? (qw + (size_t)r * 256)
            : (r < 128) ? (kw + (size_t)(r - 64) * 256)
                        : (vw + (size_t)(r - 128) * 256);
        dst = QKV + (size_t)r * 512;
    }
    store_blk(dst, c4, *(const float4*)(src + c4));
}

__global__ void __launch_bounds__(256)
conv_p1w(const float4* __restrict__ src, __nv_bfloat16* __restrict__ dst)
{
    int i = blockIdx.x * blockDim.x + threadIdx.x;
    if (i >= 256 * 80) return;
    int r = i / 80, c4 = (i - r * 80) << 2;
    store_blk(dst + (size_t)r * 640, c4, src[i]);
}

// ================= wide GEMM: 128x128 tile, cp.async 3-stage ================
// 8 warps as 4m x 2n; warp tile 32x64 (2mi x 8ni). 12 LDSM -> 48 MMA per kk.
#define G2ST_B 32768
#define G2W_OFF 16384

template<int ACT, int OUTHL>
__global__ void __launch_bounds__(256,2)
gemmW(const __nv_bfloat16* __restrict__ A, int as,
      const __nv_bfloat16* __restrict__ W, int ws,
      const float* __restrict__ bias,
      float* __restrict__ Cf, int ldc,
      __nv_bfloat16* __restrict__ Chl, int os,
      int ntiles)
{
    extern __shared__ char smc[];
    const uint32_t smb = (uint32_t)__cvta_generic_to_shared(smc);
    const int tid = threadIdx.x, lane = tid & 31, warp = tid >> 5;
    const int group = lane >> 2, tig = lane & 3;
    const int wm = warp >> 1, wn = warp & 1;
    const int m0 = blockIdx.y * 128, n0 = blockIdx.x * 128;

    const int arow = (lane & 7) + ((lane >> 3) & 1) * 8;
    const int akc  = (lane >> 4) & 1;
    const int brow = (lane & 7) + ((lane >> 4) & 1) * 8;
    const int bkc  = (lane >> 3) & 1;

    float acc[2][8][4];
    #pragma unroll
    for (int mi = 0; mi < 2; mi++)
        #pragma unroll
        for (int ni = 0; ni < 8; ni++)
            #pragma unroll
            for (int j = 0; j < 4; j++) acc[mi][ni][j] = 0.f;

    const int lrow = tid >> 3, lch = tid & 7;

    #define GW_ISSUE(t) {                                                       \
        uint32_t sb_ = smb + ((t) % 3) * G2ST_B;                                \
        _Pragma("unroll")                                                       \
        for (int i_ = 0; i_ < 4; i_++) {                                        \
            int row_ = lrow + i_ * 32;                                          \
            cp16(sb_ + swz(row_, lch),                                          \
                 A + (size_t)(m0 + row_) * as + (t) * 64 + lch * 8);            \
        }                                                                       \
        _Pragma("unroll")                                                       \
        for (int i_ = 0; i_ < 4; i_++) {                                        \
            int row_ = lrow + i_ * 32;                                          \
            cp16(sb_ + G2W_OFF + swz(row_, lch),                                \
                 W + (size_t)(n0 + row_) * ws + (t) * 64 + lch * 8);            \
        }                                                                       \
        cp_commit();                                                            \
    }

    GW_ISSUE(0);
    if (ntiles > 1) GW_ISSUE(1);

    for (int t = 0; t < ntiles; t++) {
        if (t + 1 < ntiles) cp_wait<1>(); else cp_wait<0>();
        __syncthreads();
        if (t + 2 < ntiles) GW_ISSUE(t + 2);

        const uint32_t sb = smb + (t % 3) * G2ST_B;
        #pragma unroll
        for (int kk = 0; kk < 2; kk++) {
            uint32_t aH[2][4], aL[2][4];
            #pragma unroll
            for (int mi = 0; mi < 2; mi++) {
                int r = wm * 32 + mi * 16 + arow;
                int ch = 2 * kk + akc;
                ldsm_x4(aH[mi][0], aH[mi][1], aH[mi][2], aH[mi][3], sb + swz(r, ch));
                ldsm_x4(aL[mi][0], aL[mi][1], aL[mi][2], aL[mi][3], sb + swz(r, ch + 4));
            }
            #pragma unroll
            for (int j = 0; j < 4; j++) {
                int r = wn * 64 + j * 16 + brow;
                int ch = 2 * kk + bkc;
                uint32_t bH[2][2], bL[2][2];
                ldsm_x4(bH[0][0], bH[0][1], bH[1][0], bH[1][1], sb + G2W_OFF + swz(r, ch));
                ldsm_x4(bL[0][0], bL[0][1], bL[1][0], bL[1][1], sb + G2W_OFF + swz(r, ch + 4));
                #pragma unroll
                for (int mi = 0; mi < 2; mi++)
                    #pragma unroll
                    for (int p = 0; p < 2; p++) {
                        int ni = 2 * j + p;
                        mma_bf16(acc[mi][ni], aH[mi], bL[p]);
                        mma_bf16(acc[mi][ni], aL[mi], bH[p]);
                        mma_bf16(acc[mi][ni], aH[mi], bH[p]);
                    }
            }
        }
    }
    #undef GW_ISSUE

    #pragma unroll
    for (int mi = 0; mi < 2; mi++) {
        #pragma unroll
        for (int ni = 0; ni < 8; ni++) {
            int row = m0 + wm * 32 + mi * 16 + group;
            int col = n0 + wn * 64 + ni * 8 + 2 * tig;
            float b0 = bias[col], b1 = bias[col + 1];
            float v0 = acc[mi][ni][0] + b0;
            float v1 = acc[mi][ni][1] + b1;
            float v2 = acc[mi][ni][2] + b0;
            float v3 = acc[mi][ni][3] + b1;
            if (ACT == 1) {
                v0 = fmaxf(v0, 0.f); v1 = fmaxf(v1, 0.f);
                v2 = fmaxf(v2, 0.f); v3 = fmaxf(v3, 0.f);
            }
            if (OUTHL == 0) {
                *(float2*)(Cf + (size_t)row * ldc + col)       = make_float2(v0, v1);
                *(float2*)(Cf + (size_t)(row + 8) * ldc + col) = make_float2(v2, v3);
            } else {
                int b = col >> 5, pos = col & 31;
                uint32_t h, l;
                split2(v0, v1, h, l);
                *(uint32_t*)(Chl + (size_t)row * os + b * 64 + pos)      = h;
                *(uint32_t*)(Chl + (size_t)row * os + b * 64 + 32 + pos) = l;
                split2(v2, v3, h, l);
                *(uint32_t*)(Chl + (size_t)(row + 8) * os + b * 64 + pos)      = h;
                *(uint32_t*)(Chl + (size_t)(row + 8) * os + b * 64 + 32 + pos) = l;
            }
        }
    }
}

// ================= gru_fused: gh GEMM 64x192 + GRU ==========================
#define FST_B 32768
#define FW_OFF 8192
#define STG_STRIDE 196

__global__ void __launch_bounds__(256,2)
gru_fused(const __nv_bfloat16* __restrict__ HidHL, const __nv_bfloat16* __restrict__ WhHL,
          const float* __restrict__ hidden,
          const float* __restrict__ bhh, const float* __restrict__ GI,
          __nv_bfloat16* __restrict__ cchl, float* __restrict__ hout)
{
    extern __shared__ char smc[];
    const uint32_t smb = (uint32_t)__cvta_generic_to_shared(smc);
    float* stage = (float*)smc;

    const int tid = threadIdx.x, lane = tid & 31, warp = tid >> 5;
    const int group = lane >> 2, tig = lane & 3;
    const int wm = warp >> 2, wn = warp & 3;
    const int m0 = blockIdx.y * 64, n0h = blockIdx.x * 64;

    const int arow = (lane & 7) + ((lane >> 3) & 1) * 8;
    const int akc  = (lane >> 4) & 1;
    const int brow = (lane & 7) + ((lane >> 4) & 1) * 8;
    const int bkc  = (lane >> 3) & 1;
    const int lrow = tid >> 3, lch = tid & 7;

    float acc[2][6][4];
    #pragma unroll
    for (int mi = 0; mi < 2; mi++)
        #pragma unroll
        for (int ni = 0; ni < 6; ni++)
            #pragma unroll
            for (int j = 0; j < 4; j++) acc[mi][ni][j] = 0.f;

    #define F_ISSUE(t) {                                                        \
        uint32_t sb_ = smb + ((t) % 3) * FST_B;                                 \
        _Pragma("unroll")                                                       \
        for (int i_ = 0; i_ < 2; i_++) {                                        \
            int row_ = lrow + i_ * 32;                                          \
            cp16(sb_ + swz(row_, lch),                                          \
                 HidHL + (size_t)(m0 + row_) * 512 + (t) * 64 + lch * 8);       \
        }                                                                       \
        _Pragma("unroll")                                                       \
        for (int i_ = 0; i_ < 6; i_++) {                                        \
            int row_ = lrow + i_ * 32;                                          \
            int wr_ = (row_ >> 6) * 256 + n0h + (row_ & 63);                    \
            cp16(sb_ + FW_OFF + swz(row_, lch),                                 \
                 WhHL + (size_t)wr_ * 512 + (t) * 64 + lch * 8);                \
        }                                                                       \
        cp_commit();                                                            \
    }

    F_ISSUE(0); F_ISSUE(1);

    for (int t = 0; t < 8; t++) {
        if (t + 1 < 8) cp_wait<1>(); else cp_wait<0>();
        __syncthreads();
        if (t + 2 < 8) F_ISSUE(t + 2);

        const uint32_t sb = smb + (t % 3) * FST_B;
        #pragma unroll
        for (int kk = 0; kk < 2; kk++) {
            uint32_t aH[2][4], aL[2][4];
            #pragma unroll
            for (int mi = 0; mi < 2; mi++) {
                int r = wm * 32 + mi * 16 + arow;
                int ch = 2 * kk + akc;
                ldsm_x4(aH[mi][0], aH[mi][1], aH[mi][2], aH[mi][3], sb + swz(r, ch));
                ldsm_x4(aL[mi][0], aL[mi][1], aL[mi][2], aL[mi][3], sb + swz(r, ch + 4));
            }
            #pragma unroll
            for (int j = 0; j < 3; j++) {
                int r = wn * 48 + j * 16 + brow;
                int ch = 2 * kk + bkc;
                uint32_t bH[2][2], bL[2][2];
                ldsm_x4(bH[0][0], bH[0][1], bH[1][0], bH[1][1], sb + FW_OFF + swz(r, ch));
                ldsm_x4(bL[0][0], bL[0][1], bL[1][0], bL[1][1], sb + FW_OFF + swz(r, ch + 4));
                #pragma unroll
                for (int mi = 0; mi < 2; mi++)
                    #pragma unroll
                    for (int p = 0; p < 2; p++) {
                        int ni = 2 * j + p;
                        mma_bf16(acc[mi][ni], aH[mi], bL[p]);
                        mma_bf16(acc[mi][ni], aL[mi], bH[p]);
                        mma_bf16(acc[mi][ni], aH[mi], bH[p]);
                    }
            }
        }
    }
    #undef F_ISSUE
    __syncthreads();

    #pragma unroll
    for (int mi = 0; mi < 2; mi++) {
        #pragma unroll
        for (int ni = 0; ni < 6; ni++) {
            int row = wm * 32 + mi * 16 + group;
            int col = wn * 48 + ni * 8 + 2 * tig;
            stage[row * STG_STRIDE + col]         = acc[mi][ni][0];
            stage[row * STG_STRIDE + col + 1]     = acc[mi][ni][1];
            stage[(row+8) * STG_STRIDE + col]     = acc[mi][ni][2];
            stage[(row+8) * STG_STRIDE + col + 1] = acc[mi][ni][3];
        }
    }
    __syncthreads();

    #pragma unroll
    for (int j = 0; j < 16; j++) {
        int e = tid + j * 256;
        int row = e >> 6, hcol = e & 63;
        int grow = m0 + row;
        int gcol = n0h + hcol;
        float ghr = stage[row * STG_STRIDE + hcol]       + bhh[gcol];
        float ghz = stage[row * STG_STRIDE + 64 + hcol]  + bhh[256 + gcol];
        float ghn = stage[row * STG_STRIDE + 128 + hcol] + bhh[512 + gcol];
        const float* gi = GI + (size_t)grow * 768 + gcol;
        float gir = gi[0], giz = gi[256], gin = gi[512];
        float hin = hidden[(size_t)grow * 256 + gcol];
        float r = sigm(gir + ghr);
        float z = sigm(giz + ghz);
        float n = tanhf(gin + r * ghn);
        float h = (1.f - z) * n + z * hin;
        int b = gcol >> 5, pos = gcol & 31;
        __nv_bfloat16 hb = __float2bfloat16_rn(h);
        __nv_bfloat16 lb = __float2bfloat16_rn(h - __bfloat162float(hb));
        __nv_bfloat16* dp = cchl + (size_t)grow * 640 + b * 64 + pos;
        dp[0]  = hb;
        dp[32] = lb;
        if (hout) hout[(size_t)grow * 256 + gcol] = h;
    }
}

// ================= fused q/k/v GEMM + per-batch sparse attention ============
__global__ void __launch_bounds__(256,2)
qkv_attn(const __nv_bfloat16* __restrict__ CChl, const __nv_bfloat16* __restrict__ QKVw,
         const float* __restrict__ qb, const float* __restrict__ kb,
         const float* __restrict__ vb, const float* __restrict__ gate,
         __nv_bfloat16* __restrict__ cchl_out)
{
    extern __shared__ char smc[];
    const uint32_t smb = (uint32_t)__cvta_generic_to_shared(smc);

    const int tid = threadIdx.x, lane = tid & 31, warp = tid >> 5;
    const int group = lane >> 2, tig = lane & 3;
    const int wm = warp >> 2, wn = warp & 3;
    const int m0 = blockIdx.y * 64;

    const int arow = (lane & 7) + ((lane >> 3) & 1) * 8;
    const int akc  = (lane >> 4) & 1;
    const int brow = (lane & 7) + ((lane >> 4) & 1) * 8;
    const int bkc  = (lane >> 3) & 1;
    const int lrow = tid >> 3, lch = tid & 7;

    float acc[2][6][4];
    #pragma unroll
    for (int mi = 0; mi < 2; mi++)
        #pragma unroll
        for (int ni = 0; ni < 6; ni++)
            #pragma unroll
            for (int j = 0; j < 4; j++) acc[mi][ni][j] = 0.f;

    #define Q_ISSUE(t) {                                                        \
        uint32_t sb_ = smb + ((t) % 3) * FST_B;                                 \
        _Pragma("unroll")                                                       \
        for (int i_ = 0; i_ < 2; i_++) {                                        \
            int row_ = lrow + i_ * 32;                                          \
            cp16(sb_ + swz(row_, lch),                                          \
                 CChl + (size_t)(m0 + row_) * 640 + (t) * 64 + lch * 8);        \
        }                                                                       \
        _Pragma("unroll")                                                       \
        for (int i_ = 0; i_ < 6; i_++) {                                        \
            int row_ = lrow + i_ * 32;                                          \
            cp16(sb_ + FW_OFF + swz(row_, lch),                                 \
                 QKVw + (size_t)row_ * 512 + (t) * 64 + lch * 8);               \
        }                                                                       \
        cp_commit();                                                            \
    }

    Q_ISSUE(0); Q_ISSUE(1);

    for (int t = 0; t < 8; t++) {
        if (t + 1 < 8) cp_wait<1>(); else cp_wait<0>();
        __syncthreads();
        if (t + 2 < 8) Q_ISSUE(t + 2);

        const uint32_t sb = smb + (t % 3) * FST_B;
        #pragma unroll
        for (int kk = 0; kk < 2; kk++) {
            uint32_t aH[2][4], aL[2][4];
            #pragma unroll
            for (int mi = 0; mi < 2; mi++) {
                int r = wm * 32 + mi * 16 + arow;
                int ch = 2 * kk + akc;
                ldsm_x4(aH[mi][0], aH[mi][1], aH[mi][2], aH[mi][3], sb + swz(r, ch));
                ldsm_x4(aL[mi][0], aL[mi][1], aL[mi][2], aL[mi][3], sb + swz(r, ch + 4));
            }
            #pragma unroll
            for (int j = 0; j < 3; j++) {
                int r = wn * 48 + j * 16 + brow;
                int ch = 2 * kk + bkc;
                uint32_t bH[2][2], bL[2][2];
                ldsm_x4(bH[0][0], bH[0][1], bH[1][0], bH[1][1], sb + FW_OFF + swz(r, ch));
                ldsm_x4(bL[0][0], bL[0][1], bL[1][0], bL[1][1], sb + FW_OFF + swz(r, ch + 4));
                #pragma unroll
                for (int mi = 0; mi < 2; mi++)
                    #pragma unroll
                    for (int p = 0; p < 2; p++) {
                        int ni = 2 * j + p;
                        mma_bf16(acc[mi][ni], aH[mi], bL[p]);
                        mma_bf16(acc[mi][ni], aL[mi], bH[p]);
                        mma_bf16(acc[mi][ni], aH[mi], bH[p]);
                    }
            }
        }
    }
    #undef Q_ISSUE

    __syncthreads();
    float* QS = (float*)smc;            // [64][65]
    float* KS = QS + 64*65;
    float* VS = KS + 64*65;
    float* SS = VS + 64*65;             // [8][32*33]

    #pragma unroll
    for (int mi = 0; mi < 2; mi++) {
        #pragma unroll
        for (int ni = 0; ni < 6; ni++) {
            int row = wm * 32 + mi * 16 + group;
            int col = wn * 48 + ni * 8 + 2 * tig;
            float* dst; const float* bs; int oc;
            if (col < 64)       { dst = QS; bs = qb; oc = col; }
            else if (col < 128) { dst = KS; bs = kb; oc = col - 64; }
            else                { dst = VS; bs = vb; oc = col - 128; }
            float b0 = bs[oc], b1 = bs[oc + 1];
            dst[row * 65 + oc]           = acc[mi][ni][0] + b0;
            dst[row * 65 + oc + 1]       = acc[mi][ni][1] + b1;
            dst[(row + 8) * 65 + oc]     = acc[mi][ni][2] + b0;
            dst[(row + 8) * 65 + oc + 1] = acc[mi][ni][3] + b1;
        }
    }
    __syncthreads();

    for (int i = tid; i < 8192; i += 256) {
        int b2 = i >> 12, rem = i & 4095;
        int q = rem >> 7, hk = rem & 127;
        int h = hk >> 5, k = hk & 31;
        float s;
        if (q == k) s = NEGV;
        else {
            const float* qp = QS + (b2 * 32 + q) * 65 + h * 16;
            const float* kp = KS + (b2 * 32 + k) * 65 + h * 16;
            float a = 0.f;
            #pragma unroll
            for (int d = 0; d < 16; d++) a += qp[d] * kp[d];
            s = 0.25f * a;
        }
        SS[(b2 * 4 + h) * 1056 + q * 33 + k] = s;
    }
    __syncthreads();

    {
        int b2 = tid >> 7, h = (tid >> 5) & 3, q = tid & 31;
        float* sp = SS + (b2 * 4 + h) * 1056 + q * 33;
        float v[32];
        #pragma unroll
        for (int k = 0; k < 32; k++) v[k] = sp[k];
        float maxv = -INFINITY;
        unsigned keep = 0u;
        #pragma unroll
        for (int k = 0; k < 32; k++) {
            int cnt = 0;
            #pragma unroll
            for (int j = 0; j < 32; j++) cnt += (v[j] > v[k]);
            if (cnt < TOPKN) { keep |= (1u << k); maxv = fmaxf(maxv, v[k]); }
        }
        float e[32], sum = 0.f;
        #pragma unroll
        for (int k = 0; k < 32; k++) {
            float ek = ((keep >> k) & 1u) ? expf(v[k] - maxv) : 0.f;
            e[k] = ek; sum += ek;
        }
        float inv = 1.f / sum;
        #pragma unroll
        for (int k = 0; k < 32; k++) sp[k] = e[k] * inv;
    }
    __syncthreads();

    for (int i = tid; i < 4096; i += 256) {
        int b2 = i >> 11, rem = i & 2047;
        int q = rem >> 6, hv = rem & 63, h = hv >> 4;
        const float* sp = SS + (b2 * 4 + h) * 1056 + q * 33;
        const float* vp = VS + (b2 * 32) * 65 + hv;
        float a = 0.f;
        #pragma unroll
        for (int k = 0; k < 32; k++) a += sp[k] * vp[k * 65];
        int grow = m0 + b2 * 32 + q;
        float gt = gate[(size_t)grow * NHEAD + h];
        float g = a * gt;
        int c = 256 + hv;
        int blk = c >> 5, pos = c & 31;
        __nv_bfloat16 hb = __float2bfloat16_rn(g);
        __nv_bfloat16 lb = __float2bfloat16_rn(g - __bfloat162float(hb));
        __nv_bfloat16* dp = cchl_out + (size_t)grow * 640 + blk * 64 + pos;
        dp[0]  = hb;
        dp[32] = lb;
    }
}

// ---------------- head gates ------------------------------------------------
__global__ void __launch_bounds__(256)
gate_kernel(const __nv_bfloat16* __restrict__ CChl, const float* __restrict__ gw,
            const float* __restrict__ gb, float* __restrict__ gate)
{
    int gwp  = (int)(((size_t)blockIdx.x*blockDim.x + threadIdx.x) >> 5);
    int lane = threadIdx.x & 31;
    if (gwp >= ROWS) return;
    int o = lane >> 3, part = lane & 7;
    const __nv_bfloat16* hr = CChl + (size_t)gwp * 640;
    const float* wr = gw + o * 256;
    float s = 0.f;
    #pragma unroll
    for (int j = 0; j < 8; j++) {
        int k = part * 4 + 32 * j;
        uint32_t h0 = *(const uint32_t*)(hr + j * 64 + part * 4);
        uint32_t h1 = *(const uint32_t*)(hr + j * 64 + part * 4 + 2);
        uint32_t l0 = *(const uint32_t*)(hr + j * 64 + 32 + part * 4);
        uint32_t l1 = *(const uint32_t*)(hr + j * 64 + 32 + part * 4 + 2);
        float2 a = rec2(h0, l0), b = rec2(h1, l1);
        float4 wv = *(const float4*)(wr + k);
        s += a.x*wv.x + a.y*wv.y + b.x*wv.z + b.y*wv.w;
    }
    s += __shfl_down_sync(0xffffffffu, s, 4, 8);
    s += __shfl_down_sync(0xffffffffu, s, 2, 8);
    s += __shfl_down_sync(0xffffffffu, s, 1, 8);
    if (part == 0) gate[(size_t)gwp*NHEAD + o] = sigm(s + gb[o]);
}

// ---------------- p2 head ---------------------------------------------------
__global__ void __launch_bounds__(256)
p2_kernel(const float* __restrict__ P1, const float* __restrict__ w,
          const float* __restrict__ b, float* __restrict__ out)
{
    __shared__ float WS[20*257];
    int tid = threadIdx.x;
    for (int i = tid; i < 20*256; i += 256) {
        int o = i >> 8, k = i & 255;
        WS[o*257 + k] = w[i];
    }
    __syncthreads();
    int r = tid / 20, o = tid % 20;
    int row = blockIdx.x*12 + r;
    if (tid >= 240 || row >= ROWS) return;
    const float* a  = P1 + (size_t)row*256;
    const float* wr = WS + o*257;
    float s = b[o];
    #pragma unroll 4
    for (int k = 0; k < 256; k += 4) {
        float4 av = *(const float4*)(a + k);
        s += av.x*wr[k] + av.y*wr[k+1] + av.z*wr[k+2] + av.w*wr[k+3];
    }
    out[(size_t)row*NACT + o] = s;
}

// ---------------------------------------------------------------------------
extern "C" void kernel_launch(void* const* d_in, const int* in_sizes, int n_in,
                              void* d_out, int out_size)
{
    const float* inputs = (const float*)d_in[0];
    const float* hidden = (const float*)d_in[1];
    const float* fc1_w  = (const float*)d_in[2];
    const float* fc1_b  = (const float*)d_in[3];
    const float* w_ih   = (const float*)d_in[4];
    const float* w_hh   = (const float*)d_in[5];
    const float* b_ih   = (const float*)d_in[6];
    const float* b_hh   = (const float*)d_in[7];
    const float* q_w    = (const float*)d_in[8];
    const float* q_b    = (const float*)d_in[9];
    const float* k_w    = (const float*)d_in[10];
    const float* k_b    = (const float*)d_in[11];
    const float* v_w    = (const float*)d_in[12];
    const float* v_b    = (const float*)d_in[13];
    const float* g_w    = (const float*)d_in[14];
    const float* g_b    = (const float*)d_in[15];
    const float* p1_w   = (const float*)d_in[16];
    const float* p1_b   = (const float*)d_in[17];
    const float* p2_w   = (const float*)d_in[18];
    const float* p2_b   = (const float*)d_in[19];

    float *GI, *GT, *P1;
    __nv_bfloat16 *InHL, *HidHL, *XHL, *CCHL, *W1HL, *WiHL, *WhHL, *QKVHL, *P1WHL;
    cudaGetSymbolAddress((void**)&GI, g_GI);
    cudaGetSymbolAddress((void**)&GT, g_GT);
    cudaGetSymbolAddress((void**)&P1, g_P1);
    cudaGetSymbolAddress((void**)&InHL,  g_InHL);
    cudaGetSymbolAddress((void**)&HidHL, g_HidHL);
    cudaGetSymbolAddress((void**)&XHL,   g_XHL);
    cudaGetSymbolAddress((void**)&CCHL,  g_CCHL);
    cudaGetSymbolAddress((void**)&W1HL,  g_W1HL);
    cudaGetSymbolAddress((void**)&WiHL,  g_WiHL);
    cudaGetSymbolAddress((void**)&WhHL,  g_WhHL);
    cudaGetSymbolAddress((void**)&QKVHL, g_QKVHL);
    cudaGetSymbolAddress((void**)&P1WHL, g_P1WHL);

    float* out  = (float*)d_out;
    float* hout = nullptr;
    long long need = (long long)ROWS*NACT + (long long)ROWS*HIDN;
    if ((long long)out_size >= need) hout = out + (size_t)ROWS*NACT;

    const int g2sm = 3 * G2ST_B;  // 98304
    const int fsm  = 3 * FST_B;   // 98304
    static int smem_set = 0;
    if (!smem_set) {
        cudaFuncSetAttribute(gemmW<0,0>, cudaFuncAttributeMaxDynamicSharedMemorySize, g2sm);
        cudaFuncSetAttribute(gemmW<1,0>, cudaFuncAttributeMaxDynamicSharedMemorySize, g2sm);
        cudaFuncSetAttribute(gemmW<1,1>, cudaFuncAttributeMaxDynamicSharedMemorySize, g2sm);
        cudaFuncSetAttribute(gru_fused, cudaFuncAttributeMaxDynamicSharedMemorySize, fsm);
        cudaFuncSetAttribute(qkv_attn, cudaFuncAttributeMaxDynamicSharedMemorySize, fsm);
        smem_set = 1;
    }

    dim3 thr(256);

    // 0) conversions (3 launches)
    conv_acts<<<(2*ROWS*64 + 255)/256, thr>>>((const float4*)inputs, InHL,
                                              (const float4*)hidden, HidHL);
    conv_wts<<<(1984*64 + 255)/256, thr>>>(fc1_w, w_ih, w_hh, q_w, k_w, v_w,
                                           W1HL, WiHL, WhHL, QKVHL);
    conv_p1w<<<(256*80 + 255)/256, thr>>>((const float4*)p1_w, P1WHL);

    // 1) x = relu(inputs @ fc1_w^T + fc1_b) -> XHL
    gemmW<1,1><<<dim3(2, ROWS/128), thr, g2sm>>>(InHL, 512, W1HL, 512, fc1_b,
                                                 nullptr, 0, XHL, 512, 8);
    // 2) gi = x @ W_ih^T + b_ih -> GI (f32)
    gemmW<0,0><<<dim3(6, ROWS/128), thr, g2sm>>>(XHL, 512, WiHL, 512, b_ih,
                                                 GI, 768, nullptr, 0, 8);
    // 3) fused gh GEMM + GRU -> CCHL blocks 0-7 + hout
    gru_fused<<<dim3(4, ROWS/64), thr, fsm>>>(HidHL, WhHL, hidden, b_hh, GI, CCHL, hout);
    // 4) head gates
    gate_kernel<<<(ROWS*32)/256, thr>>>(CCHL, g_w, g_b, GT);
    // 5) fused q/k/v GEMM + sparse attention -> CCHL blocks 8-9
    qkv_attn<<<dim3(1, ROWS/64), thr, fsm>>>(CCHL, QKVHL, q_b, k_b, v_b, GT, CCHL);
    // 6) p1 = relu(CC @ p1_w^T + p1_b) -> P1 (f32)
    gemmW<1,0><<<dim3(2, ROWS/128), thr, g2sm>>>(CCHL, 640, P1WHL, 640, p1_b,
                                                 P1, 256, nullptr, 0, 10);
    // 7) logits
    p2_kernel<<<(ROWS + 11)/12, thr>>>(P1, p2_w, p2_b, out);
}